// round 15
// baseline (speedup 1.0000x reference)
#include <cuda_runtime.h>
#include <cuda_bf16.h>
#include <cstdint>
#include <cstddef>

#define NT 300000
#define NC 100000
#define NM 20000
typedef unsigned int u32; typedef unsigned long long u64;
typedef __nv_bfloat16 bf;

// ---------------- fp32 scratch ----------------
static constexpr size_t F_TF=0,
 F_HT1=F_TF+(size_t)NT*128, F_HT2=F_HT1+(size_t)NT*128,
 F_HC=F_HT2+(size_t)NT*128, F_HM=F_HC+(size_t)NC*128,
 F_SC=F_HM+(size_t)NM*128,  F_SM=F_SC+(size_t)NC*128,
 F_GC=F_SM+(size_t)NM*128,  F_GM=F_GC+(size_t)NC*64,
 F_Q2=F_GM+(size_t)NM*64,   F_RSC=F_Q2+(size_t)NT*64,
 F_RSM=F_RSC+NC, F_TOT=F_RSM+NM;
__device__ float g_f[F_TOT];

// ---------------- bf16 scratch ----------------
static constexpr size_t
 B_P1H=0,                     B_P1L=B_P1H+(size_t)NT*256,
 B_P2H=B_P1L+(size_t)NT*256,  B_P2L=B_P2H+(size_t)NT*256,
 B_ACH=B_P2L+(size_t)NT*256,  B_ACL=B_ACH+(size_t)NC*128,
 B_AMH=B_ACL+(size_t)NC*128,  B_AML=B_AMH+(size_t)NM*128,
 B_TH=B_AML+(size_t)NM*128,   B_TL=B_TH+(size_t)NT*64,
 B_Q1H=B_TL+(size_t)NT*64,    B_Q1L=B_Q1H+(size_t)NT*64,
 SZ_P1=(size_t)256*416, SZ_P2=65536, SZ_P3=32768, SZ_CV=16384, SZ_C3=8192, SZ_PO=4096,
 W_P1=B_Q1L+(size_t)NT*64,
 W_P2=W_P1+2*SZ_P1, W_P3=W_P2+2*SZ_P2,
 W_C1=W_P3+2*SZ_P3,
 W_C2=W_C1+8*SZ_CV, W_C3=W_C2+8*SZ_CV,
 W_PI=W_C3+4*SZ_C3, W_PH=W_PI+2*SZ_PO,
 B_TOT=W_PH+2*SZ_PO;
__device__ bf g_b[B_TOT];

// ---------------- PTX helpers ----------------
__device__ __forceinline__ u32 smem_u32(const void* p){
    u32 a; asm("{ .reg .u64 t; cvta.to.shared.u64 t, %1; cvt.u32.u64 %0, t; }":"=r"(a):"l"(p));
    return a;
}
__device__ __forceinline__ u32 packpair(float a, float b){ // low half=a, high=b
    u32 r; asm("cvt.rn.bf16x2.f32 %0, %1, %2;" : "=r"(r) : "f"(b), "f"(a)); return r;
}
__device__ __forceinline__ float bflo(u32 p){ return __uint_as_float(p<<16); }
__device__ __forceinline__ float bfhi(u32 p){ return __uint_as_float(p&0xFFFF0000u); }

__device__ __forceinline__ void cpa16(u32 dst, const void* src, int sz){
    asm volatile("cp.async.cg.shared.global [%0], [%1], 16, %2;"
                 :: "r"(dst), "l"(src), "r"(sz) : "memory");
}
#define CP_COMMIT() asm volatile("cp.async.commit_group;" ::: "memory")
#define CP_WAIT(n)  asm volatile("cp.async.wait_group %0;" :: "n"(n) : "memory")
#define STS128(a,x0,x1,x2,x3) asm volatile("st.shared.v4.b32 [%0], {%1,%2,%3,%4};" :: "r"(a), "r"(x0),"r"(x1),"r"(x2),"r"(x3))

__device__ __forceinline__ void ldm4(u32* d, u32 a){
    asm volatile("ldmatrix.sync.aligned.m8n8.x4.shared.b16 {%0,%1,%2,%3}, [%4];"
        : "=r"(d[0]),"=r"(d[1]),"=r"(d[2]),"=r"(d[3]) : "r"(a));
}
__device__ __forceinline__ void mma16816(float* c, const u32* a, const u32* b){
    asm volatile("mma.sync.aligned.m16n8k16.row.col.f32.bf16.bf16.f32 "
        "{%0,%1,%2,%3}, {%4,%5,%6,%7}, {%8,%9}, {%0,%1,%2,%3};"
        : "+f"(c[0]),"+f"(c[1]),"+f"(c[2]),"+f"(c[3])
        : "r"(a[0]),"r"(a[1]),"r"(a[2]),"r"(a[3]), "r"(b[0]),"r"(b[1]));
}

// ---------------- small kernels ----------------
__global__ void zero_kernel(float* p, int n)
{
    int i = blockIdx.x*blockDim.x + threadIdx.x;
    if (i < n) p[i] = 0.f;
}
// W fp32 [K,N] row-major -> transposed H/L bf16 [N,Kpad]; batched over blockIdx.y
__global__ void wsplit_kernel(const float* __restrict__ W0, int K, int N, int Kpad,
                              size_t wstride, size_t ostride,
                              bf* __restrict__ H0, bf* __restrict__ L0)
{
    int b = blockIdx.y;
    const float* W = W0 + (size_t)b*wstride;
    bf* H = H0 + (size_t)b*ostride;
    bf* L = L0 + (size_t)b*ostride;
    int i = blockIdx.x*blockDim.x + threadIdx.x;
    int hp = Kpad>>1;
    if (i >= N*hp) return;
    int n = i/hp, k = (i%hp)*2;
    float a0 = (k   < K) ? W[(size_t)k*N+n]     : 0.f;
    float a1 = (k+1 < K) ? W[(size_t)(k+1)*N+n] : 0.f;
    u32 h = packpair(a0,a1);
    u32 l = packpair(a0-bflo(h), a1-bfhi(h));
    *(u32*)(H + (size_t)n*Kpad + k) = h;
    *(u32*)(L + (size_t)n*Kpad + k) = l;
}

// ---------------- mma.sync GEMM ----------------
// C[M, tile BNT of ldC] = A(hi+lo)[M,*] @ Wt(hi+lo)[N,Kpad]^T
// CVTA=false: A given as bf16 hi/lo pair (Aptr=AH, AL), stride Ald (=Kpad).
// CVTA=true : A given fp32 (stride Ald, real width Kreal, optional row prescale preA).
// CTA 128 x BNT, 256 threads (8 warps, 4x2), BK=32,
// 3-buffer cp.async pipeline, ONE __syncthreads per stage; 2 CTAs/SM.
// Hoisted ldmatrix addressing + interleaved hi/lo load-MMA phases.
template<int BNT, bool CVTA>
__global__ void __launch_bounds__(256, 2)
hgemm_kernel(const void* __restrict__ Aptr, const bf* __restrict__ AL,
             const bf* __restrict__ BH, const bf* __restrict__ BL,
             int M, int Kpad, int Ald, int Kreal, int ldC,
             const float* __restrict__ preA,
             const float* __restrict__ bias, const float* __restrict__ sC, int relu,
             float* __restrict__ outF, bf* __restrict__ outH, bf* __restrict__ outL,
             const float* __restrict__ esc)
{
    extern __shared__ char smem[];
    constexpr int STG = 16384 + BNT*128;     // A(hi+lo) 16KB + B(hi+lo)
    constexpr int WN  = BNT/2;
    constexpr int NTI = WN/8;
    const u32 smb = smem_u32(smem);
    const int tid = threadIdx.x, w = tid>>5, l = tid&31;
    const int wm = w>>1, wn = w&1;
    const int row0 = blockIdx.y*128;
    const int col0 = blockIdx.x*BNT;

    const bf* AHb = (const bf*)Aptr;
    const float* Af = (const float*)Aptr;
    const bf* Bh = BH + (size_t)col0*Kpad;
    const bf* Bl = BL + (size_t)col0*Kpad;

    const int nst = Kpad >> 5;
    float aReg[16];

    // hoisted ldmatrix offsets (ks=0); ks=1 address = offset ^ 32
    u32 aoff[2], boff[NTI/2];
#pragma unroll
    for (int mt = 0; mt < 2; mt++) {
        int r = wm*32 + mt*16 + (l&15);
        int ch = (l>>4) ^ ((r>>1)&3);
        aoff[mt] = (u32)(r*64 + ch*16);
    }
#pragma unroll
    for (int tp2 = 0; tp2 < NTI/2; tp2++) {
        int r  = wn*WN + (tp2*2 + (l>>4))*8 + (l&7);
        int ch = ((l>>3)&1) ^ ((r>>1)&3);
        boff[tp2] = (u32)(16384 + r*64 + ch*16);
    }

    auto ldgA = [&](int st){
        if (!CVTA) return;
        const int k0 = st<<5;
#pragma unroll
        for (int j = 0; j < 2; j++) {
            int i = tid*2 + j;
            int r = i>>2, cch = i&3;
            int gr = row0 + r;
            float* v = aReg + j*8;
            if (gr < M) {
                const float* p = Af + (size_t)gr*Ald + k0 + cch*8;
                int kb = k0 + cch*8;
                if ((Ald&3)==0 && kb + 8 <= Kreal) {
                    float4 q0 = *(const float4*)p, q1 = *(const float4*)(p+4);
                    v[0]=q0.x; v[1]=q0.y; v[2]=q0.z; v[3]=q0.w;
                    v[4]=q1.x; v[5]=q1.y; v[6]=q1.z; v[7]=q1.w;
                } else {
#pragma unroll
                    for (int e = 0; e < 4; e++) {
                        int k = kb + 2*e;
                        if (k + 2 <= Kreal) {
                            float2 q = *(const float2*)(p + 2*e);
                            v[2*e] = q.x; v[2*e+1] = q.y;
                        } else if (k < Kreal) {
                            v[2*e] = p[2*e]; v[2*e+1] = 0.f;
                        } else { v[2*e] = 0.f; v[2*e+1] = 0.f; }
                    }
                }
                if (preA) {
                    float s = preA[gr];
#pragma unroll
                    for (int e = 0; e < 8; e++) v[e] *= s;
                }
            } else {
#pragma unroll
                for (int e = 0; e < 8; e++) v[e] = 0.f;
            }
        }
    };
    auto stsA = [&](int buf){
        if (!CVTA) return;
        const u32 sb = smb + buf*STG;
#pragma unroll
        for (int j = 0; j < 2; j++) {
            int i = tid*2 + j;
            int r = i>>2, cch = i&3;
            float* v = aReg + j*8;
            u32 h[4], lo[4];
#pragma unroll
            for (int e = 0; e < 4; e++) {
                h[e]  = packpair(v[2*e], v[2*e+1]);
                lo[e] = packpair(v[2*e]-bflo(h[e]), v[2*e+1]-bfhi(h[e]));
            }
            u32 d = sb + r*64 + ((u32)(cch ^ ((r>>1)&3))<<4);
            STS128(d,        h[0],h[1],h[2],h[3]);
            STS128(d + 8192, lo[0],lo[1],lo[2],lo[3]);
        }
    };
    auto issue = [&](int st, int buf){
        const u32 sb = smb + buf*STG;
        const int k0 = st<<5;
        if (!CVTA) {
            for (int i = tid; i < 512; i += 256) {        // A: 128 rows x 4 chunks
                int r = i>>2, cch = i&3;
                int gr = row0 + r;
                int grc = gr < M ? gr : 0;
                int sz  = gr < M ? 16 : 0;
                u32 d = sb + r*64 + ((u32)(cch ^ ((r>>1)&3))<<4);
                cpa16(d,        AHb + (size_t)grc*Ald + k0 + cch*8, sz);
                cpa16(d + 8192, AL  + (size_t)grc*Ald + k0 + cch*8, sz);
            }
        }
        for (int i = tid; i < BNT*4; i += 256) {          // B: BNT rows x 4 chunks
            int r = i>>2, cch = i&3;
            u32 d = sb + 16384 + r*64 + ((u32)(cch ^ ((r>>1)&3))<<4);
            cpa16(d,          Bh + (size_t)r*Kpad + k0 + cch*8, 16);
            cpa16(d + BNT*64, Bl + (size_t)r*Kpad + k0 + cch*8, 16);
        }
        CP_COMMIT();
    };

    float acc[2][NTI][4];
#pragma unroll
    for (int mt = 0; mt < 2; mt++)
#pragma unroll
        for (int nt = 0; nt < NTI; nt++)
#pragma unroll
            for (int q = 0; q < 4; q++) acc[mt][nt][q] = 0.f;

    ldgA(0);
    issue(0, 0);
    if (nst > 1) issue(1, 1);

    int bufc = 0;
    for (int c = 0; c < nst; c++) {
        if (c + 1 < nst) CP_WAIT(1); else CP_WAIT(0);
        if (CVTA) {
            stsA(bufc);                      // writes buf c%3 (last read at stage c-3)
            if (c + 1 < nst) ldgA(c + 1);
        }
        __syncthreads();                     // the ONLY barrier per stage
        // buffer (c+2)%3 was consumed at stage c-1; refill now so the cp.async
        // overlaps this stage's MMAs.
        if (c + 2 < nst) {
            int nb = bufc + 2; if (nb >= 3) nb -= 3;
            issue(c + 2, nb);
        }
        const u32 sa = smb + bufc*STG;
#pragma unroll
        for (int ks = 0; ks < 2; ks++) {
            const u32 kx = (u32)(ks << 5);   // ks toggles address bit 5
            // hi loads
            u32 ah[2][4];
#pragma unroll
            for (int mt = 0; mt < 2; mt++) ldm4(ah[mt], sa + (aoff[mt] ^ kx));
            u32 bh2[NTI][2];
#pragma unroll
            for (int tp2 = 0; tp2 < NTI/2; tp2++) {
                u32 t4[4]; ldm4(t4, sa + (boff[tp2] ^ kx));
                bh2[tp2*2][0]=t4[0]; bh2[tp2*2][1]=t4[1];
                bh2[tp2*2+1][0]=t4[2]; bh2[tp2*2+1][1]=t4[3];
            }
            // hh MMAs (fragments ready soonest) — lo loads issued after,
            // spreading smem traffic across the tensor burst
#pragma unroll
            for (int mt = 0; mt < 2; mt++)
#pragma unroll
                for (int nt = 0; nt < NTI; nt++)
                    mma16816(acc[mt][nt], ah[mt], bh2[nt]);
            // lo loads
            u32 al2[2][4];
#pragma unroll
            for (int mt = 0; mt < 2; mt++) ldm4(al2[mt], sa + (aoff[mt] ^ kx) + 8192);
            u32 bl2[NTI][2];
#pragma unroll
            for (int tp2 = 0; tp2 < NTI/2; tp2++) {
                u32 t5[4]; ldm4(t5, sa + (boff[tp2] ^ kx) + BNT*64);
                bl2[tp2*2][0]=t5[0]; bl2[tp2*2][1]=t5[1];
                bl2[tp2*2+1][0]=t5[2]; bl2[tp2*2+1][1]=t5[3];
            }
#pragma unroll
            for (int mt = 0; mt < 2; mt++)
#pragma unroll
                for (int nt = 0; nt < NTI; nt++)
                    mma16816(acc[mt][nt], ah[mt], bl2[nt]);
#pragma unroll
            for (int mt = 0; mt < 2; mt++)
#pragma unroll
                for (int nt = 0; nt < NTI; nt++)
                    mma16816(acc[mt][nt], al2[mt], bh2[nt]);
        }
        bufc = (bufc == 2) ? 0 : bufc + 1;
    }

    // epilogue
#pragma unroll
    for (int mt = 0; mt < 2; mt++)
#pragma unroll
        for (int hf = 0; hf < 2; hf++) {
            int r = row0 + wm*32 + mt*16 + (l>>2) + hf*8;
            if (r >= M) continue;
            float scv = sC  ? sC[r]  : 1.f;
            float e   = esc ? esc[r] : 1.f;
#pragma unroll
            for (int nt = 0; nt < NTI; nt++) {
                int col = col0 + wn*WN + nt*8 + (l&3)*2;
                float v0 = acc[mt][nt][hf*2], v1 = acc[mt][nt][hf*2+1];
                if (sC)   { v0 *= scv; v1 *= scv; }
                if (bias) { v0 += bias[col]; v1 += bias[col+1]; }
                if (relu) { v0 = fmaxf(v0,0.f); v1 = fmaxf(v1,0.f); }
                if (outF) *(float2*)(outF + (size_t)r*ldC + col) = make_float2(v0,v1);
                if (outH) {
                    float a0 = v0*e, a1 = v1*e;
                    u32 h = packpair(a0,a1);
                    u32 lo = packpair(a0-bflo(h), a1-bfhi(h));
                    *(u32*)(outH + (size_t)r*ldC + col) = h;
                    *(u32*)(outL + (size_t)r*ldC + col) = lo;
                }
            }
        }
}

// ---------------- graph-side kernels ----------------
__global__ void deg_count_kernel(const int* __restrict__ cid, const int* __restrict__ mid,
                                 float* degC, float* degM, int n)
{
    int i = blockIdx.x*blockDim.x + threadIdx.x;
    if (i < n) { atomicAdd(&degC[cid[i]], 1.f); atomicAdd(&degM[mid[i]], 1.f); }
}
__global__ void rsqrt_kernel(float* d, int n)
{
    int i = blockIdx.x*blockDim.x + threadIdx.x;
    if (i < n) d[i] = rsqrtf(fmaxf(d[i], 1.f));
}
__global__ void gather_kernel(const float* __restrict__ hc, const float* __restrict__ hm,
                              const int* __restrict__ cid, const int* __restrict__ mid,
                              const float* __restrict__ ba, const float* __restrict__ bb,
                              float* __restrict__ out, int n)
{
    int w = (blockIdx.x*blockDim.x + threadIdx.x)>>5, lane = threadIdx.x&31;
    if (w >= n) return;
    int c = cid[w], m = mid[w];
    int col = lane*4;
    float4 x = *(const float4*)(hc + (size_t)c*128 + col);
    float4 y = *(const float4*)(hm + (size_t)m*128 + col);
    float4 u = *(const float4*)(ba + col);
    float4 v = *(const float4*)(bb + col);
    float4 r;
    r.x = fmaxf(x.x+y.x+u.x+v.x, 0.f); r.y = fmaxf(x.y+y.y+u.y+v.y, 0.f);
    r.z = fmaxf(x.z+y.z+u.z+v.z, 0.f); r.w = fmaxf(x.w+y.w+u.w+v.w, 0.f);
    *(float4*)(out + (size_t)w*128 + col) = r;
}
__global__ void gather_hl_kernel(const float* __restrict__ gc, const float* __restrict__ gm,
                                 const int* __restrict__ cid, const int* __restrict__ mid,
                                 const float* __restrict__ ba, const float* __restrict__ bb,
                                 bf* __restrict__ oh, bf* __restrict__ ol, int n)
{
    int w = (blockIdx.x*blockDim.x + threadIdx.x)>>5, lane = threadIdx.x&31;
    if (w >= n) return;
    int c = cid[w], m = mid[w];
    float2 x = *(const float2*)(gc + (size_t)c*64 + lane*2);
    float2 y = *(const float2*)(gm + (size_t)m*64 + lane*2);
    float2 u = *(const float2*)(ba + lane*2);
    float2 v = *(const float2*)(bb + lane*2);
    float a0 = x.x+y.x+u.x+v.x, a1 = x.y+y.y+u.y+v.y;
    u32 h = packpair(a0,a1);
    u32 l = packpair(a0-bflo(h), a1-bfhi(h));
    *(u32*)(oh + (size_t)w*64 + lane*2) = h;
    *(u32*)(ol + (size_t)w*64 + lane*2) = l;
}
__global__ void segsum_kernel(const float* __restrict__ src,
                              const int* __restrict__ cid, const int* __restrict__ mid,
                              float* outC, float* outM, int n)
{
    int w = (blockIdx.x*blockDim.x + threadIdx.x)>>5, lane = threadIdx.x&31;
    if (w >= n) return;
    float4 v = *(const float4*)(src + (size_t)w*128 + lane*4);
    float* pc = outC + (size_t)cid[w]*128 + lane*4;
    float* pm = outM + (size_t)mid[w]*128 + lane*4;
    asm volatile("red.relaxed.gpu.global.add.v4.f32 [%0], {%1,%2,%3,%4};" :: "l"(pc),"f"(v.x),"f"(v.y),"f"(v.z),"f"(v.w) : "memory");
    asm volatile("red.relaxed.gpu.global.add.v4.f32 [%0], {%1,%2,%3,%4};" :: "l"(pm),"f"(v.x),"f"(v.y),"f"(v.z),"f"(v.w) : "memory");
}
__global__ void dot_scatter_kernel(const float* __restrict__ ht,
                                   const int* __restrict__ cid, const int* __restrict__ mid,
                                   const float* __restrict__ w3,
                                   float* outC, float* outM, int n)
{
    int w = (blockIdx.x*blockDim.x + threadIdx.x)>>5, lane = threadIdx.x&31;
    if (w >= n) return;
    float4 x  = *(const float4*)(ht + (size_t)w*128 + lane*4);
    float4 w0 = *(const float4*)(w3 + lane*4);
    float4 w1 = *(const float4*)(w3 + 128 + lane*4);
    float s0 = x.x*w0.x + x.y*w0.y + x.z*w0.z + x.w*w0.w;
    float s1 = x.x*w1.x + x.y*w1.y + x.z*w1.z + x.w*w1.w;
#pragma unroll
    for (int o = 16; o; o >>= 1) {
        s0 += __shfl_xor_sync(0xffffffffu, s0, o);
        s1 += __shfl_xor_sync(0xffffffffu, s1, o);
    }
    if (lane == 0) { atomicAdd(&outC[cid[w]], s0); atomicAdd(&outM[mid[w]], s1); }
}
__global__ void finalize_cm_kernel(float* outC, float* outM,
                                   const float* __restrict__ rsC, const float* __restrict__ rsM,
                                   const float* __restrict__ bo, int nc, int nm)
{
    int i = blockIdx.x*blockDim.x + threadIdx.x;
    if (i < nc)              outC[i]    = outC[i]*rsC[i] + bo[0];
    else if (i < nc + nm)    outM[i-nc] = outM[i-nc]*rsM[i-nc] + bo[1];
}
__global__ void gemv64_kernel(const float* __restrict__ A, const float* __restrict__ w,
                              const float* __restrict__ b, float* __restrict__ out, int n)
{
    int r = (blockIdx.x*blockDim.x + threadIdx.x)>>5, lane = threadIdx.x&31;
    if (r >= n) return;
    float2 x  = *(const float2*)(A + (size_t)r*64 + lane*2);
    float2 ww = *(const float2*)(w + lane*2);
    float s = x.x*ww.x + x.y*ww.y;
#pragma unroll
    for (int o = 16; o; o >>= 1) s += __shfl_xor_sync(0xffffffffu, s, o);
    if (lane == 0) out[r] = s + b[0];
}

// ---------------- host ----------------
static void tgb(int BN, const bf* AH, const bf* AL, const bf* BH, const bf* BL,
                int M, int Kpad, const float* bias, const float* sC, int relu,
                float* outF, bf* outH, bf* outL, const float* esc)
{
    if (BN >= 128) {
        dim3 g(BN/128, (M + 127)/128);
        size_t sm = 3*(16384 + 128*128);
        cudaFuncSetAttribute(hgemm_kernel<128,false>, cudaFuncAttributeMaxDynamicSharedMemorySize, (int)sm);
        hgemm_kernel<128,false><<<g, 256, sm>>>(AH,AL,BH,BL,M,Kpad,Kpad,Kpad,BN,nullptr,bias,sC,relu,outF,outH,outL,esc);
    } else {
        dim3 g(1, (M + 127)/128);
        size_t sm = 3*(16384 + 64*128);
        cudaFuncSetAttribute(hgemm_kernel<64,false>, cudaFuncAttributeMaxDynamicSharedMemorySize, (int)sm);
        hgemm_kernel<64,false><<<g, 256, sm>>>(AH,AL,BH,BL,M,Kpad,Kpad,Kpad,BN,nullptr,bias,sC,relu,outF,outH,outL,esc);
    }
}
static void tgc(int BN, const float* A, const bf* BH, const bf* BL,
                int M, int Kpad, int Ald, int Kreal, const float* preA,
                const float* bias, const float* sC, int relu,
                float* outF, bf* outH, bf* outL, const float* esc)
{
    if (BN >= 128) {
        dim3 g(BN/128, (M + 127)/128);
        size_t sm = 3*(16384 + 128*128);
        cudaFuncSetAttribute(hgemm_kernel<128,true>, cudaFuncAttributeMaxDynamicSharedMemorySize, (int)sm);
        hgemm_kernel<128,true><<<g, 256, sm>>>(A,nullptr,BH,BL,M,Kpad,Ald,Kreal,BN,preA,bias,sC,relu,outF,outH,outL,esc);
    } else {
        dim3 g(1, (M + 127)/128);
        size_t sm = 3*(16384 + 64*128);
        cudaFuncSetAttribute(hgemm_kernel<64,true>, cudaFuncAttributeMaxDynamicSharedMemorySize, (int)sm);
        hgemm_kernel<64,true><<<g, 256, sm>>>(A,nullptr,BH,BL,M,Kpad,Ald,Kreal,BN,preA,bias,sC,relu,outF,outH,outL,esc);
    }
}
static void wsp(const float* W, int K, int N, int Kpad, bf* H, bf* L,
                int count = 1, size_t wstride = 0, size_t ostride = 0)
{
    int n = N*(Kpad/2);
    dim3 g((n + 255)/256, count);
    wsplit_kernel<<<g, 256>>>(W, K, N, Kpad, wstride, ostride, H, L);
}

extern "C" void kernel_launch(void* const* d_in, const int* in_sizes, int n_in,
                              void* d_out, int out_size)
{
    const float* X      = (const float*)d_in[0];
    const int*   cid    = (const int*)  d_in[1];
    const int*   mid    = (const int*)  d_in[2];
    const float* cardE  = (const float*)d_in[3];
    const float* merchE = (const float*)d_in[4];
    const float* preWi  = (const float*)d_in[5];
    const float* preBi  = (const float*)d_in[6];
    const float* preWh  = (const float*)d_in[7];
    const float* preBh  = (const float*)d_in[8];
    const float* preWo  = (const float*)d_in[9];
    const float* preBo  = (const float*)d_in[10];
    const float* c1W    = (const float*)d_in[11];
    const float* c1b    = (const float*)d_in[12];
    const float* c2W    = (const float*)d_in[13];
    const float* c2b    = (const float*)d_in[14];
    const float* c3Wt   = (const float*)d_in[15];
    const float* c3bt   = (const float*)d_in[16];
    const float* c3Wo   = (const float*)d_in[17];
    const float* c3bo   = (const float*)d_in[18];
    const float* poWi   = (const float*)d_in[19];
    const float* poBi   = (const float*)d_in[20];
    const float* poWh   = (const float*)d_in[21];
    const float* poBh   = (const float*)d_in[22];
    const float* poWo   = (const float*)d_in[23];
    const float* poBo   = (const float*)d_in[24];
    float* out = (float*)d_out;

    float* F = nullptr; bf* B = nullptr;
    cudaGetSymbolAddress((void**)&F, g_f);
    cudaGetSymbolAddress((void**)&B, g_b);

    float *TF=F+F_TF, *HT1=F+F_HT1, *HT2=F+F_HT2, *HC=F+F_HC, *HM=F+F_HM,
          *SC=F+F_SC, *SM=F+F_SM, *GC=F+F_GC, *GM=F+F_GM, *Q2=F+F_Q2,
          *rsC=F+F_RSC, *rsM=F+F_RSM;

    const int wpr = (NT*32 + 255)/256;

    // launches 1-3
    wsp(preWi, 390, 256, 416, B+W_P1, B+W_P1+SZ_P1);                 // 1
    zero_kernel<<<(NC+NM+255)/256, 256>>>(rsC, NC+NM);               // 2
    deg_count_kernel<<<(NT+255)/256, 256>>>(cid, mid, rsC, rsM, NT); // 3
    // launch 4 (ncu captures kernel launch #4): dominant pre-FF GEMM, fused X split
    tgc(256, X, B+W_P1, B+W_P1+SZ_P1, NT, 416, 390, 390, nullptr,
        preBi, nullptr, 1, nullptr, B+B_P1H, B+B_P1L, nullptr);      // 4
    rsqrt_kernel<<<(NC+NM+255)/256, 256>>>(rsC, NC+NM);              // 5

    // remaining weight splits (batched)
    wsp(preWh, 256, 256, 256, B+W_P2, B+W_P2+SZ_P2);
    wsp(preWo, 256, 128, 256, B+W_P3, B+W_P3+SZ_P3);
    wsp(c1W, 128, 128, 128, B+W_C1, B+W_C1+SZ_CV, 4, 16384, 2*SZ_CV);
    wsp(c2W, 128, 128, 128, B+W_C2, B+W_C2+SZ_CV, 4, 16384, 2*SZ_CV);
    wsp(c3Wt, 128, 64, 128, B+W_C3, B+W_C3+SZ_C3, 2, 8192, 2*SZ_C3);
    wsp(poWi, 64, 64, 64, B+W_PI, B+W_PI+SZ_PO);
    wsp(poWh, 64, 64, 64, B+W_PH, B+W_PH+SZ_PO);

    // pre-FF rest: 256->256->128
    tgb(256, B+B_P1H, B+B_P1L, B+W_P2, B+W_P2+SZ_P2, NT, 256, preBh, nullptr, 1, nullptr, B+B_P2H, B+B_P2L, nullptr);
    tgb(128, B+B_P2H, B+B_P2L, B+W_P3, B+W_P3+SZ_P3, NT, 256, preBo, nullptr, 0, TF, nullptr, nullptr, nullptr);

    // conv1 (embeddings fp32 + degree prescale, fused split)
    tgc(128, cardE,  B+W_C1+0*2*SZ_CV, B+W_C1+0*2*SZ_CV+SZ_CV, NC, 128, 128, 128, rsC,
        nullptr, nullptr, 0, HC, nullptr, nullptr, nullptr);
    tgc(128, merchE, B+W_C1+1*2*SZ_CV, B+W_C1+1*2*SZ_CV+SZ_CV, NM, 128, 128, 128, rsM,
        nullptr, nullptr, 0, HM, nullptr, nullptr, nullptr);
    gather_kernel<<<wpr, 256>>>(HC, HM, cid, mid, c1b, c1b+128, HT1, NT);

    cudaMemsetAsync(SC, 0, (size_t)(NC+NM)*128*4, 0);
    segsum_kernel<<<wpr, 256>>>(TF, cid, mid, SC, SM, NT);
    tgc(128, SC, B+W_C1+2*2*SZ_CV, B+W_C1+2*2*SZ_CV+SZ_CV, NC, 128, 128, 128, nullptr,
        c1b+256, rsC, 1, nullptr, B+B_ACH, B+B_ACL, rsC);
    tgc(128, SM, B+W_C1+3*2*SZ_CV, B+W_C1+3*2*SZ_CV+SZ_CV, NM, 128, 128, 128, nullptr,
        c1b+384, rsM, 1, nullptr, B+B_AMH, B+B_AML, rsM);

    // conv2
    tgb(128, B+B_ACH, B+B_ACL, B+W_C2+0*2*SZ_CV, B+W_C2+0*2*SZ_CV+SZ_CV, NC, 128, nullptr, nullptr, 0, HC, nullptr, nullptr, nullptr);
    tgb(128, B+B_AMH, B+B_AML, B+W_C2+1*2*SZ_CV, B+W_C2+1*2*SZ_CV+SZ_CV, NM, 128, nullptr, nullptr, 0, HM, nullptr, nullptr, nullptr);
    gather_kernel<<<wpr, 256>>>(HC, HM, cid, mid, c2b, c2b+128, HT2, NT);

    cudaMemsetAsync(SC, 0, (size_t)(NC+NM)*128*4, 0);
    segsum_kernel<<<wpr, 256>>>(HT1, cid, mid, SC, SM, NT);
    tgc(128, SC, B+W_C2+2*2*SZ_CV, B+W_C2+2*2*SZ_CV+SZ_CV, NC, 128, 128, 128, nullptr,
        c2b+256, rsC, 1, nullptr, B+B_ACH, B+B_ACL, rsC);
    tgc(128, SM, B+W_C2+3*2*SZ_CV, B+W_C2+3*2*SZ_CV+SZ_CV, NM, 128, 128, 128, nullptr,
        c2b+384, rsM, 1, nullptr, B+B_AMH, B+B_AML, rsM);

    // conv3 target-side: D_OUT=64
    tgb(64, B+B_ACH, B+B_ACL, B+W_C3+0*2*SZ_C3, B+W_C3+0*2*SZ_C3+SZ_C3, NC, 128, nullptr, nullptr, 0, GC, nullptr, nullptr, nullptr);
    tgb(64, B+B_AMH, B+B_AML, B+W_C3+1*2*SZ_C3, B+W_C3+1*2*SZ_C3+SZ_C3, NM, 128, nullptr, nullptr, 0, GM, nullptr, nullptr, nullptr);
    gather_hl_kernel<<<wpr, 256>>>(GC, GM, cid, mid, c3bt, c3bt+64, B+B_TH, B+B_TL, NT);

    // conv3 non-target heads
    cudaMemsetAsync(out + NT, 0, (size_t)(NC+NM)*4, 0);
    dot_scatter_kernel<<<wpr, 256>>>(HT2, cid, mid, c3Wo, out+NT, out+NT+NC, NT);
    finalize_cm_kernel<<<(NC+NM+255)/256, 256>>>(out+NT, out+NT+NC, rsC, rsM, c3bo, NC, NM);

    // post-FF: 64->64->64->1
    tgb(64, B+B_TH,  B+B_TL,  B+W_PI, B+W_PI+SZ_PO, NT, 64, poBi, nullptr, 1, nullptr, B+B_Q1H, B+B_Q1L, nullptr);
    tgb(64, B+B_Q1H, B+B_Q1L, B+W_PH, B+W_PH+SZ_PO, NT, 64, poBh, nullptr, 1, Q2, nullptr, nullptr, nullptr);
    gemv64_kernel<<<wpr, 256>>>(Q2, poWo, poBo, out, NT);
}

// round 16
// speedup vs baseline: 1.0659x; 1.0659x over previous
#include <cuda_runtime.h>
#include <cuda_bf16.h>
#include <cstdint>
#include <cstddef>

#define NT 300000
#define NC 100000
#define NM 20000
typedef unsigned int u32; typedef unsigned long long u64;
typedef __nv_bfloat16 bf;

// ---------------- fp32 scratch ----------------
static constexpr size_t
 F_HC=0,                    F_HM=F_HC+(size_t)NC*128,
 F_SC=F_HM+(size_t)NM*128,  F_SM=F_SC+(size_t)NC*128,
 F_GC=F_SM+(size_t)NM*128,  F_GM=F_GC+(size_t)NC*64,
 F_Q2=F_GM+(size_t)NM*64,   F_RSC=F_Q2+(size_t)NT*64,
 F_RSM=F_RSC+NC, F_TOT=F_RSM+NM;
__device__ float g_f[F_TOT];

// ---------------- bf16 scratch ----------------
static constexpr size_t
 B_P1H=0,                     B_P1L=B_P1H+(size_t)NT*256,
 B_P2H=B_P1L+(size_t)NT*256,  B_P2L=B_P2H+(size_t)NT*256,
 B_ACH=B_P2L+(size_t)NT*256,  B_ACL=B_ACH+(size_t)NC*128,
 B_AMH=B_ACL+(size_t)NC*128,  B_AML=B_AMH+(size_t)NM*128,
 B_TH=B_AML+(size_t)NM*128,   B_TL=B_TH+(size_t)NT*64,
 B_Q1H=B_TL+(size_t)NT*64,    B_Q1L=B_Q1H+(size_t)NT*64,
 SZ_P1=(size_t)256*416, SZ_P2=65536, SZ_P3=32768, SZ_CV=16384, SZ_C3=8192, SZ_PO=4096,
 W_P1=B_Q1L+(size_t)NT*64,
 W_P2=W_P1+2*SZ_P1, W_P3=W_P2+2*SZ_P2,
 W_C1=W_P3+2*SZ_P3,
 W_C2=W_C1+8*SZ_CV, W_C3=W_C2+8*SZ_CV,
 W_PI=W_C3+4*SZ_C3, W_PH=W_PI+2*SZ_PO,
 B_TOT=W_PH+2*SZ_PO;
__device__ bf g_b[B_TOT];

// ---------------- PTX helpers ----------------
__device__ __forceinline__ u32 smem_u32(const void* p){
    u32 a; asm("{ .reg .u64 t; cvta.to.shared.u64 t, %1; cvt.u32.u64 %0, t; }":"=r"(a):"l"(p));
    return a;
}
__device__ __forceinline__ u32 packpair(float a, float b){ // low half=a, high=b
    u32 r; asm("cvt.rn.bf16x2.f32 %0, %1, %2;" : "=r"(r) : "f"(b), "f"(a)); return r;
}
__device__ __forceinline__ float bflo(u32 p){ return __uint_as_float(p<<16); }
__device__ __forceinline__ float bfhi(u32 p){ return __uint_as_float(p&0xFFFF0000u); }

__device__ __forceinline__ void cpa16(u32 dst, const void* src, int sz){
    asm volatile("cp.async.cg.shared.global [%0], [%1], 16, %2;"
                 :: "r"(dst), "l"(src), "r"(sz) : "memory");
}
#define CP_COMMIT() asm volatile("cp.async.commit_group;" ::: "memory")
#define CP_WAIT(n)  asm volatile("cp.async.wait_group %0;" :: "n"(n) : "memory")
#define STS128(a,x0,x1,x2,x3) asm volatile("st.shared.v4.b32 [%0], {%1,%2,%3,%4};" :: "r"(a), "r"(x0),"r"(x1),"r"(x2),"r"(x3))

__device__ __forceinline__ void ldm4(u32* d, u32 a){
    asm volatile("ldmatrix.sync.aligned.m8n8.x4.shared.b16 {%0,%1,%2,%3}, [%4];"
        : "=r"(d[0]),"=r"(d[1]),"=r"(d[2]),"=r"(d[3]) : "r"(a));
}
__device__ __forceinline__ void mma16816(float* c, const u32* a, const u32* b){
    asm volatile("mma.sync.aligned.m16n8k16.row.col.f32.bf16.bf16.f32 "
        "{%0,%1,%2,%3}, {%4,%5,%6,%7}, {%8,%9}, {%0,%1,%2,%3};"
        : "+f"(c[0]),"+f"(c[1]),"+f"(c[2]),"+f"(c[3])
        : "r"(a[0]),"r"(a[1]),"r"(a[2]),"r"(a[3]), "r"(b[0]),"r"(b[1]));
}
__device__ __forceinline__ void redadd2(float* p, float a, float b){
    asm volatile("red.relaxed.gpu.global.add.v2.f32 [%0], {%1,%2};"
                 :: "l"(p), "f"(a), "f"(b) : "memory");
}

// ---------------- small kernels ----------------
__global__ void zero_kernel(float* p, size_t n)
{
    size_t i = (size_t)blockIdx.x*blockDim.x + threadIdx.x;
    if (i < n) p[i] = 0.f;
}
// W fp32 [K,N] row-major -> transposed H/L bf16 [N,Kpad]; batched over blockIdx.y
__global__ void wsplit_kernel(const float* __restrict__ W0, int K, int N, int Kpad,
                              size_t wstride, size_t ostride,
                              bf* __restrict__ H0, bf* __restrict__ L0)
{
    int b = blockIdx.y;
    const float* W = W0 + (size_t)b*wstride;
    bf* H = H0 + (size_t)b*ostride;
    bf* L = L0 + (size_t)b*ostride;
    int i = blockIdx.x*blockDim.x + threadIdx.x;
    int hp = Kpad>>1;
    if (i >= N*hp) return;
    int n = i/hp, k = (i%hp)*2;
    float a0 = (k   < K) ? W[(size_t)k*N+n]     : 0.f;
    float a1 = (k+1 < K) ? W[(size_t)(k+1)*N+n] : 0.f;
    u32 h = packpair(a0,a1);
    u32 l = packpair(a0-bflo(h), a1-bfhi(h));
    *(u32*)(H + (size_t)n*Kpad + k) = h;
    *(u32*)(L + (size_t)n*Kpad + k) = l;
}

// ---------------- mma.sync GEMM ----------------
// CTA 128 x BNT, 256 threads (8 warps, 4x2), BK=32,
// 3-buffer cp.async pipeline, ONE __syncthreads per stage; 2 CTAs/SM.
// Epilogue modes: outF (plain fp32), outH/outL (bf16 hi/lo with esc scale),
// or scC/scM scatter: red.add rows into scC[scid[r]]/scM[smid[r]] (stride 128).
template<int BNT, bool CVTA>
__global__ void __launch_bounds__(256, 2)
hgemm_kernel(const void* __restrict__ Aptr, const bf* __restrict__ AL,
             const bf* __restrict__ BH, const bf* __restrict__ BL,
             int M, int Kpad, int Ald, int Kreal, int ldC,
             const float* __restrict__ preA,
             const float* __restrict__ bias, const float* __restrict__ sC, int relu,
             float* __restrict__ outF, bf* __restrict__ outH, bf* __restrict__ outL,
             const float* __restrict__ esc,
             const int* __restrict__ scid, const int* __restrict__ smid,
             float* __restrict__ scC, float* __restrict__ scM)
{
    extern __shared__ char smem[];
    constexpr int STG = 16384 + BNT*128;     // A(hi+lo) 16KB + B(hi+lo)
    constexpr int WN  = BNT/2;
    constexpr int NTI = WN/8;
    const u32 smb = smem_u32(smem);
    const int tid = threadIdx.x, w = tid>>5, l = tid&31;
    const int wm = w>>1, wn = w&1;
    const int row0 = blockIdx.y*128;
    const int col0 = blockIdx.x*BNT;

    const bf* AHb = (const bf*)Aptr;
    const float* Af = (const float*)Aptr;
    const bf* Bh = BH + (size_t)col0*Kpad;
    const bf* Bl = BL + (size_t)col0*Kpad;

    const int nst = Kpad >> 5;
    float aReg[16];

    auto ldgA = [&](int st){
        if (!CVTA) return;
        const int k0 = st<<5;
#pragma unroll
        for (int j = 0; j < 2; j++) {
            int i = tid*2 + j;
            int r = i>>2, cch = i&3;
            int gr = row0 + r;
            float* v = aReg + j*8;
            if (gr < M) {
                const float* p = Af + (size_t)gr*Ald + k0 + cch*8;
                int kb = k0 + cch*8;
                if ((Ald&3)==0 && kb + 8 <= Kreal) {
                    float4 q0 = *(const float4*)p, q1 = *(const float4*)(p+4);
                    v[0]=q0.x; v[1]=q0.y; v[2]=q0.z; v[3]=q0.w;
                    v[4]=q1.x; v[5]=q1.y; v[6]=q1.z; v[7]=q1.w;
                } else {
#pragma unroll
                    for (int e = 0; e < 4; e++) {
                        int k = kb + 2*e;
                        if (k + 2 <= Kreal) {
                            float2 q = *(const float2*)(p + 2*e);
                            v[2*e] = q.x; v[2*e+1] = q.y;
                        } else if (k < Kreal) {
                            v[2*e] = p[2*e]; v[2*e+1] = 0.f;
                        } else { v[2*e] = 0.f; v[2*e+1] = 0.f; }
                    }
                }
                if (preA) {
                    float s = preA[gr];
#pragma unroll
                    for (int e = 0; e < 8; e++) v[e] *= s;
                }
            } else {
#pragma unroll
                for (int e = 0; e < 8; e++) v[e] = 0.f;
            }
        }
    };
    auto stsA = [&](int buf){
        if (!CVTA) return;
        const u32 sb = smb + buf*STG;
#pragma unroll
        for (int j = 0; j < 2; j++) {
            int i = tid*2 + j;
            int r = i>>2, cch = i&3;
            float* v = aReg + j*8;
            u32 h[4], lo[4];
#pragma unroll
            for (int e = 0; e < 4; e++) {
                h[e]  = packpair(v[2*e], v[2*e+1]);
                lo[e] = packpair(v[2*e]-bflo(h[e]), v[2*e+1]-bfhi(h[e]));
            }
            u32 d = sb + r*64 + ((u32)(cch ^ ((r>>1)&3))<<4);
            STS128(d,        h[0],h[1],h[2],h[3]);
            STS128(d + 8192, lo[0],lo[1],lo[2],lo[3]);
        }
    };
    auto issue = [&](int st, int buf){
        const u32 sb = smb + buf*STG;
        const int k0 = st<<5;
        if (!CVTA) {
            for (int i = tid; i < 512; i += 256) {        // A: 128 rows x 4 chunks
                int r = i>>2, cch = i&3;
                int gr = row0 + r;
                int grc = gr < M ? gr : 0;
                int sz  = gr < M ? 16 : 0;
                u32 d = sb + r*64 + ((u32)(cch ^ ((r>>1)&3))<<4);
                cpa16(d,        AHb + (size_t)grc*Ald + k0 + cch*8, sz);
                cpa16(d + 8192, AL  + (size_t)grc*Ald + k0 + cch*8, sz);
            }
        }
        for (int i = tid; i < BNT*4; i += 256) {          // B: BNT rows x 4 chunks
            int r = i>>2, cch = i&3;
            u32 d = sb + 16384 + r*64 + ((u32)(cch ^ ((r>>1)&3))<<4);
            cpa16(d,          Bh + (size_t)r*Kpad + k0 + cch*8, 16);
            cpa16(d + BNT*64, Bl + (size_t)r*Kpad + k0 + cch*8, 16);
        }
        CP_COMMIT();
    };

    float acc[2][NTI][4];
#pragma unroll
    for (int mt = 0; mt < 2; mt++)
#pragma unroll
        for (int nt = 0; nt < NTI; nt++)
#pragma unroll
            for (int q = 0; q < 4; q++) acc[mt][nt][q] = 0.f;

    ldgA(0);
    issue(0, 0);
    if (nst > 1) issue(1, 1);

    int bufc = 0;
    for (int c = 0; c < nst; c++) {
        if (c + 1 < nst) CP_WAIT(1); else CP_WAIT(0);
        if (CVTA) {
            stsA(bufc);
            if (c + 1 < nst) ldgA(c + 1);
        }
        __syncthreads();                     // the ONLY barrier per stage
        if (c + 2 < nst) {
            int nb = bufc + 2; if (nb >= 3) nb -= 3;
            issue(c + 2, nb);
        }
        const u32 sa  = smb + bufc*STG;
        const u32 sbB = sa + 16384;
#pragma unroll
        for (int ks = 0; ks < 2; ks++) {
            u32 ah[2][4], al2[2][4];
#pragma unroll
            for (int mt = 0; mt < 2; mt++) {
                int r  = wm*32 + mt*16 + (l&15);
                int ch = (ks*2 + (l>>4)) ^ ((r>>1)&3);
                u32 ad = sa + r*64 + ch*16;
                ldm4(ah[mt],  ad);
                ldm4(al2[mt], ad + 8192);
            }
            u32 bh2[NTI][2], bl2[NTI][2];
#pragma unroll
            for (int tp = 0; tp < NTI; tp += 2) {
                int r  = wn*WN + (tp + (l>>4))*8 + (l&7);
                int ch = (ks*2 + ((l>>3)&1)) ^ ((r>>1)&3);
                u32 ad = sbB + r*64 + ch*16;
                u32 t4[4]; ldm4(t4, ad);
                bh2[tp][0]=t4[0]; bh2[tp][1]=t4[1]; bh2[tp+1][0]=t4[2]; bh2[tp+1][1]=t4[3];
                u32 t5[4]; ldm4(t5, ad + BNT*64);
                bl2[tp][0]=t5[0]; bl2[tp][1]=t5[1]; bl2[tp+1][0]=t5[2]; bl2[tp+1][1]=t5[3];
            }
#pragma unroll
            for (int mt = 0; mt < 2; mt++)
#pragma unroll
                for (int nt = 0; nt < NTI; nt++)
                    mma16816(acc[mt][nt], ah[mt], bh2[nt]);
#pragma unroll
            for (int mt = 0; mt < 2; mt++)
#pragma unroll
                for (int nt = 0; nt < NTI; nt++)
                    mma16816(acc[mt][nt], ah[mt], bl2[nt]);
#pragma unroll
            for (int mt = 0; mt < 2; mt++)
#pragma unroll
                for (int nt = 0; nt < NTI; nt++)
                    mma16816(acc[mt][nt], al2[mt], bh2[nt]);
        }
        bufc = (bufc == 2) ? 0 : bufc + 1;
    }

    // epilogue
#pragma unroll
    for (int mt = 0; mt < 2; mt++)
#pragma unroll
        for (int hf = 0; hf < 2; hf++) {
            int r = row0 + wm*32 + mt*16 + (l>>2) + hf*8;
            if (r >= M) continue;
            float scv = sC  ? sC[r]  : 1.f;
            float e   = esc ? esc[r] : 1.f;
            int ci = 0, mi = 0;
            if (scC) { ci = scid[r]; mi = smid[r]; }
#pragma unroll
            for (int nt = 0; nt < NTI; nt++) {
                int col = col0 + wn*WN + nt*8 + (l&3)*2;
                float v0 = acc[mt][nt][hf*2], v1 = acc[mt][nt][hf*2+1];
                if (sC)   { v0 *= scv; v1 *= scv; }
                if (bias) { v0 += bias[col]; v1 += bias[col+1]; }
                if (relu) { v0 = fmaxf(v0,0.f); v1 = fmaxf(v1,0.f); }
                if (scC) {
                    redadd2(scC + (size_t)ci*128 + col, v0, v1);
                    redadd2(scM + (size_t)mi*128 + col, v0, v1);
                }
                if (outF) *(float2*)(outF + (size_t)r*ldC + col) = make_float2(v0,v1);
                if (outH) {
                    float a0 = v0*e, a1 = v1*e;
                    u32 h = packpair(a0,a1);
                    u32 lo = packpair(a0-bflo(h), a1-bfhi(h));
                    *(u32*)(outH + (size_t)r*ldC + col) = h;
                    *(u32*)(outL + (size_t)r*ldC + col) = lo;
                }
            }
        }
}

// ---------------- graph-side kernels ----------------
__global__ void deg_count_kernel(const int* __restrict__ cid, const int* __restrict__ mid,
                                 float* degC, float* degM, int n)
{
    int i = blockIdx.x*blockDim.x + threadIdx.x;
    if (i < n) { atomicAdd(&degC[cid[i]], 1.f); atomicAdd(&degM[mid[i]], 1.f); }
}
__global__ void rsqrt_kernel(float* d, int n)
{
    int i = blockIdx.x*blockDim.x + threadIdx.x;
    if (i < n) d[i] = rsqrtf(fmaxf(d[i], 1.f));
}
// fused gather + segsum: z = relu(hc[c]+hm[m]+ba+bb); red.add z into outC[c], outM[m]
__global__ void gather_segsum_kernel(const float* __restrict__ hc, const float* __restrict__ hm,
                                     const int* __restrict__ cid, const int* __restrict__ mid,
                                     const float* __restrict__ ba, const float* __restrict__ bb,
                                     float* outC, float* outM, int n)
{
    int w = (blockIdx.x*blockDim.x + threadIdx.x)>>5, lane = threadIdx.x&31;
    if (w >= n) return;
    int c = cid[w], m = mid[w];
    int col = lane*4;
    float4 x = *(const float4*)(hc + (size_t)c*128 + col);
    float4 y = *(const float4*)(hm + (size_t)m*128 + col);
    float4 u = *(const float4*)(ba + col);
    float4 v = *(const float4*)(bb + col);
    float z0 = fmaxf(x.x+y.x+u.x+v.x, 0.f), z1 = fmaxf(x.y+y.y+u.y+v.y, 0.f);
    float z2 = fmaxf(x.z+y.z+u.z+v.z, 0.f), z3 = fmaxf(x.w+y.w+u.w+v.w, 0.f);
    float* pc = outC + (size_t)c*128 + col;
    float* pm = outM + (size_t)m*128 + col;
    asm volatile("red.relaxed.gpu.global.add.v4.f32 [%0], {%1,%2,%3,%4};" :: "l"(pc),"f"(z0),"f"(z1),"f"(z2),"f"(z3) : "memory");
    asm volatile("red.relaxed.gpu.global.add.v4.f32 [%0], {%1,%2,%3,%4};" :: "l"(pm),"f"(z0),"f"(z1),"f"(z2),"f"(z3) : "memory");
}
// fused gather + conv3 non-target dot-scatter: z = relu(hc[c]+hm[m]+ba+bb);
// s0 = z . w3[0:128], s1 = z . w3[128:256]; atomicAdd into outC[c], outM[m]
__global__ void gather_dot_kernel(const float* __restrict__ hc, const float* __restrict__ hm,
                                  const int* __restrict__ cid, const int* __restrict__ mid,
                                  const float* __restrict__ ba, const float* __restrict__ bb,
                                  const float* __restrict__ w3,
                                  float* outC, float* outM, int n)
{
    int w = (blockIdx.x*blockDim.x + threadIdx.x)>>5, lane = threadIdx.x&31;
    if (w >= n) return;
    int c = cid[w], m = mid[w];
    int col = lane*4;
    float4 x = *(const float4*)(hc + (size_t)c*128 + col);
    float4 y = *(const float4*)(hm + (size_t)m*128 + col);
    float4 u = *(const float4*)(ba + col);
    float4 v = *(const float4*)(bb + col);
    float z0 = fmaxf(x.x+y.x+u.x+v.x, 0.f), z1 = fmaxf(x.y+y.y+u.y+v.y, 0.f);
    float z2 = fmaxf(x.z+y.z+u.z+v.z, 0.f), z3 = fmaxf(x.w+y.w+u.w+v.w, 0.f);
    float4 w0 = *(const float4*)(w3 + col);
    float4 w1 = *(const float4*)(w3 + 128 + col);
    float s0 = z0*w0.x + z1*w0.y + z2*w0.z + z3*w0.w;
    float s1 = z0*w1.x + z1*w1.y + z2*w1.z + z3*w1.w;
#pragma unroll
    for (int o = 16; o; o >>= 1) {
        s0 += __shfl_xor_sync(0xffffffffu, s0, o);
        s1 += __shfl_xor_sync(0xffffffffu, s1, o);
    }
    if (lane == 0) { atomicAdd(&outC[c], s0); atomicAdd(&outM[m], s1); }
}
// dim-64 gather emitting bf16 hi/lo (no relu) for the post-FF input
__global__ void gather_hl_kernel(const float* __restrict__ gc, const float* __restrict__ gm,
                                 const int* __restrict__ cid, const int* __restrict__ mid,
                                 const float* __restrict__ ba, const float* __restrict__ bb,
                                 bf* __restrict__ oh, bf* __restrict__ ol, int n)
{
    int w = (blockIdx.x*blockDim.x + threadIdx.x)>>5, lane = threadIdx.x&31;
    if (w >= n) return;
    int c = cid[w], m = mid[w];
    float2 x = *(const float2*)(gc + (size_t)c*64 + lane*2);
    float2 y = *(const float2*)(gm + (size_t)m*64 + lane*2);
    float2 u = *(const float2*)(ba + lane*2);
    float2 v = *(const float2*)(bb + lane*2);
    float a0 = x.x+y.x+u.x+v.x, a1 = x.y+y.y+u.y+v.y;
    u32 h = packpair(a0,a1);
    u32 l = packpair(a0-bflo(h), a1-bfhi(h));
    *(u32*)(oh + (size_t)w*64 + lane*2) = h;
    *(u32*)(ol + (size_t)w*64 + lane*2) = l;
}
__global__ void finalize_cm_kernel(float* outC, float* outM,
                                   const float* __restrict__ rsC, const float* __restrict__ rsM,
                                   const float* __restrict__ bo, int nc, int nm)
{
    int i = blockIdx.x*blockDim.x + threadIdx.x;
    if (i < nc)              outC[i]    = outC[i]*rsC[i] + bo[0];
    else if (i < nc + nm)    outM[i-nc] = outM[i-nc]*rsM[i-nc] + bo[1];
}
__global__ void gemv64_kernel(const float* __restrict__ A, const float* __restrict__ w,
                              const float* __restrict__ b, float* __restrict__ out, int n)
{
    int r = (blockIdx.x*blockDim.x + threadIdx.x)>>5, lane = threadIdx.x&31;
    if (r >= n) return;
    float2 x  = *(const float2*)(A + (size_t)r*64 + lane*2);
    float2 ww = *(const float2*)(w + lane*2);
    float s = x.x*ww.x + x.y*ww.y;
#pragma unroll
    for (int o = 16; o; o >>= 1) s += __shfl_xor_sync(0xffffffffu, s, o);
    if (lane == 0) out[r] = s + b[0];
}

// ---------------- host ----------------
static void tgb(int BN, const bf* AH, const bf* AL, const bf* BH, const bf* BL,
                int M, int Kpad, const float* bias, const float* sC, int relu,
                float* outF, bf* outH, bf* outL, const float* esc,
                const int* scid = nullptr, const int* smid = nullptr,
                float* scC = nullptr, float* scM = nullptr)
{
    if (BN >= 128) {
        dim3 g(BN/128, (M + 127)/128);
        size_t sm = 3*(16384 + 128*128);
        cudaFuncSetAttribute(hgemm_kernel<128,false>, cudaFuncAttributeMaxDynamicSharedMemorySize, (int)sm);
        hgemm_kernel<128,false><<<g, 256, sm>>>(AH,AL,BH,BL,M,Kpad,Kpad,Kpad,BN,nullptr,bias,sC,relu,outF,outH,outL,esc,scid,smid,scC,scM);
    } else {
        dim3 g(1, (M + 127)/128);
        size_t sm = 3*(16384 + 64*128);
        cudaFuncSetAttribute(hgemm_kernel<64,false>, cudaFuncAttributeMaxDynamicSharedMemorySize, (int)sm);
        hgemm_kernel<64,false><<<g, 256, sm>>>(AH,AL,BH,BL,M,Kpad,Kpad,Kpad,BN,nullptr,bias,sC,relu,outF,outH,outL,esc,scid,smid,scC,scM);
    }
}
static void tgc(int BN, const float* A, const bf* BH, const bf* BL,
                int M, int Kpad, int Ald, int Kreal, const float* preA,
                const float* bias, const float* sC, int relu,
                float* outF, bf* outH, bf* outL, const float* esc)
{
    if (BN >= 128) {
        dim3 g(BN/128, (M + 127)/128);
        size_t sm = 3*(16384 + 128*128);
        cudaFuncSetAttribute(hgemm_kernel<128,true>, cudaFuncAttributeMaxDynamicSharedMemorySize, (int)sm);
        hgemm_kernel<128,true><<<g, 256, sm>>>(A,nullptr,BH,BL,M,Kpad,Ald,Kreal,BN,preA,bias,sC,relu,outF,outH,outL,esc,nullptr,nullptr,nullptr,nullptr);
    } else {
        dim3 g(1, (M + 127)/128);
        size_t sm = 3*(16384 + 64*128);
        cudaFuncSetAttribute(hgemm_kernel<64,true>, cudaFuncAttributeMaxDynamicSharedMemorySize, (int)sm);
        hgemm_kernel<64,true><<<g, 256, sm>>>(A,nullptr,BH,BL,M,Kpad,Ald,Kreal,BN,preA,bias,sC,relu,outF,outH,outL,esc,nullptr,nullptr,nullptr,nullptr);
    }
}
static void wsp(const float* W, int K, int N, int Kpad, bf* H, bf* L,
                int count = 1, size_t wstride = 0, size_t ostride = 0)
{
    int n = N*(Kpad/2);
    dim3 g((n + 255)/256, count);
    wsplit_kernel<<<g, 256>>>(W, K, N, Kpad, wstride, ostride, H, L);
}

extern "C" void kernel_launch(void* const* d_in, const int* in_sizes, int n_in,
                              void* d_out, int out_size)
{
    const float* X      = (const float*)d_in[0];
    const int*   cid    = (const int*)  d_in[1];
    const int*   mid    = (const int*)  d_in[2];
    const float* cardE  = (const float*)d_in[3];
    const float* merchE = (const float*)d_in[4];
    const float* preWi  = (const float*)d_in[5];
    const float* preBi  = (const float*)d_in[6];
    const float* preWh  = (const float*)d_in[7];
    const float* preBh  = (const float*)d_in[8];
    const float* preWo  = (const float*)d_in[9];
    const float* preBo  = (const float*)d_in[10];
    const float* c1W    = (const float*)d_in[11];
    const float* c1b    = (const float*)d_in[12];
    const float* c2W    = (const float*)d_in[13];
    const float* c2b    = (const float*)d_in[14];
    const float* c3Wt   = (const float*)d_in[15];
    const float* c3bt   = (const float*)d_in[16];
    const float* c3Wo   = (const float*)d_in[17];
    const float* c3bo   = (const float*)d_in[18];
    const float* poWi   = (const float*)d_in[19];
    const float* poBi   = (const float*)d_in[20];
    const float* poWh   = (const float*)d_in[21];
    const float* poBh   = (const float*)d_in[22];
    const float* poWo   = (const float*)d_in[23];
    const float* poBo   = (const float*)d_in[24];
    float* out = (float*)d_out;

    float* F = nullptr; bf* B = nullptr;
    cudaGetSymbolAddress((void**)&F, g_f);
    cudaGetSymbolAddress((void**)&B, g_b);

    float *HC=F+F_HC, *HM=F+F_HM, *SC=F+F_SC, *SM=F+F_SM,
          *GC=F+F_GC, *GM=F+F_GM, *Q2=F+F_Q2, *rsC=F+F_RSC, *rsM=F+F_RSM;

    const int wpr = (NT*32 + 255)/256;

    // launches 1-3
    wsp(preWi, 390, 256, 416, B+W_P1, B+W_P1+SZ_P1);                 // 1
    zero_kernel<<<(NC+NM+255)/256, 256>>>(rsC, NC+NM);               // 2
    deg_count_kernel<<<(NT+255)/256, 256>>>(cid, mid, rsC, rsM, NT); // 3
    // launch 4 (ncu capture slot): dominant pre-FF GEMM, fused X split
    tgc(256, X, B+W_P1, B+W_P1+SZ_P1, NT, 416, 390, 390, nullptr,
        preBi, nullptr, 1, nullptr, B+B_P1H, B+B_P1L, nullptr);      // 4
    rsqrt_kernel<<<(NC+NM+255)/256, 256>>>(rsC, NC+NM);              // 5

    // remaining weight splits (batched)
    wsp(preWh, 256, 256, 256, B+W_P2, B+W_P2+SZ_P2);
    wsp(preWo, 256, 128, 256, B+W_P3, B+W_P3+SZ_P3);
    wsp(c1W, 128, 128, 128, B+W_C1, B+W_C1+SZ_CV, 4, 16384, 2*SZ_CV);
    wsp(c2W, 128, 128, 128, B+W_C2, B+W_C2+SZ_CV, 4, 16384, 2*SZ_CV);
    wsp(c3Wt, 128, 64, 128, B+W_C3, B+W_C3+SZ_C3, 2, 8192, 2*SZ_C3);
    wsp(poWi, 64, 64, 64, B+W_PI, B+W_PI+SZ_PO);
    wsp(poWh, 64, 64, 64, B+W_PH, B+W_PH+SZ_PO);

    // zero SC/SM ahead of the scatter-epilogue GEMM3
    zero_kernel<<<(unsigned)(((size_t)(NC+NM)*128 + 255)/256), 256>>>(SC, (size_t)(NC+NM)*128);

    // pre-FF rest: 256->256, then 256->128 with fused segsum#1 scatter (TF eliminated)
    tgb(256, B+B_P1H, B+B_P1L, B+W_P2, B+W_P2+SZ_P2, NT, 256, preBh, nullptr, 1, nullptr, B+B_P2H, B+B_P2L, nullptr);
    tgb(128, B+B_P2H, B+B_P2L, B+W_P3, B+W_P3+SZ_P3, NT, 256, preBo, nullptr, 0,
        nullptr, nullptr, nullptr, nullptr, cid, mid, SC, SM);

    // conv1 fwd (embeddings fp32 + degree prescale, fused split)
    tgc(128, cardE,  B+W_C1+0*2*SZ_CV, B+W_C1+0*2*SZ_CV+SZ_CV, NC, 128, 128, 128, rsC,
        nullptr, nullptr, 0, HC, nullptr, nullptr, nullptr);
    tgc(128, merchE, B+W_C1+1*2*SZ_CV, B+W_C1+1*2*SZ_CV+SZ_CV, NM, 128, 128, 128, rsM,
        nullptr, nullptr, 0, HM, nullptr, nullptr, nullptr);

    // conv1 rev GEMMs consume SC/SM
    tgc(128, SC, B+W_C1+2*2*SZ_CV, B+W_C1+2*2*SZ_CV+SZ_CV, NC, 128, 128, 128, nullptr,
        c1b+256, rsC, 1, nullptr, B+B_ACH, B+B_ACL, rsC);
    tgc(128, SM, B+W_C1+3*2*SZ_CV, B+W_C1+3*2*SZ_CV+SZ_CV, NM, 128, 128, 128, nullptr,
        c1b+384, rsM, 1, nullptr, B+B_AMH, B+B_AML, rsM);

    // segsum#2 fused with gather1 (HT1 eliminated): re-zero SC/SM, then
    // scatter relu(conv1-target rows) built from HC/HM (still conv1 data)
    zero_kernel<<<(unsigned)(((size_t)(NC+NM)*128 + 255)/256), 256>>>(SC, (size_t)(NC+NM)*128);
    gather_segsum_kernel<<<wpr, 256>>>(HC, HM, cid, mid, c1b, c1b+128, SC, SM, NT);

    // conv2 fwd (overwrites HC/HM — safe now)
    tgb(128, B+B_ACH, B+B_ACL, B+W_C2+0*2*SZ_CV, B+W_C2+0*2*SZ_CV+SZ_CV, NC, 128, nullptr, nullptr, 0, HC, nullptr, nullptr, nullptr);
    tgb(128, B+B_AMH, B+B_AML, B+W_C2+1*2*SZ_CV, B+W_C2+1*2*SZ_CV+SZ_CV, NM, 128, nullptr, nullptr, 0, HM, nullptr, nullptr, nullptr);

    // conv3 non-target heads fused with gather2 (HT2 eliminated)
    cudaMemsetAsync(out + NT, 0, (size_t)(NC+NM)*4, 0);
    gather_dot_kernel<<<wpr, 256>>>(HC, HM, cid, mid, c2b, c2b+128, c3Wo, out+NT, out+NT+NC, NT);

    // conv2 rev GEMMs
    tgc(128, SC, B+W_C2+2*2*SZ_CV, B+W_C2+2*2*SZ_CV+SZ_CV, NC, 128, 128, 128, nullptr,
        c2b+256, rsC, 1, nullptr, B+B_ACH, B+B_ACL, rsC);
    tgc(128, SM, B+W_C2+3*2*SZ_CV, B+W_C2+3*2*SZ_CV+SZ_CV, NM, 128, 128, 128, nullptr,
        c2b+384, rsM, 1, nullptr, B+B_AMH, B+B_AML, rsM);

    // conv3 target-side: D_OUT=64
    tgb(64, B+B_ACH, B+B_ACL, B+W_C3+0*2*SZ_C3, B+W_C3+0*2*SZ_C3+SZ_C3, NC, 128, nullptr, nullptr, 0, GC, nullptr, nullptr, nullptr);
    tgb(64, B+B_AMH, B+B_AML, B+W_C3+1*2*SZ_C3, B+W_C3+1*2*SZ_C3+SZ_C3, NM, 128, nullptr, nullptr, 0, GM, nullptr, nullptr, nullptr);
    gather_hl_kernel<<<wpr, 256>>>(GC, GM, cid, mid, c3bt, c3bt+64, B+B_TH, B+B_TL, NT);

    finalize_cm_kernel<<<(NC+NM+255)/256, 256>>>(out+NT, out+NT+NC, rsC, rsM, c3bo, NC, NM);

    // post-FF: 64->64->64->1
    tgb(64, B+B_TH,  B+B_TL,  B+W_PI, B+W_PI+SZ_PO, NT, 64, poBi, nullptr, 1, nullptr, B+B_Q1H, B+B_Q1L, nullptr);
    tgb(64, B+B_Q1H, B+B_Q1L, B+W_PH, B+W_PH+SZ_PO, NT, 64, poBh, nullptr, 1, Q2, nullptr, nullptr, nullptr);
    gemv64_kernel<<<wpr, 256>>>(Q2, poWo, poBo, out, NT);
}

// round 17
// speedup vs baseline: 1.0696x; 1.0035x over previous
#include <cuda_runtime.h>
#include <cuda_bf16.h>
#include <cstdint>
#include <cstddef>

#define NT 300000
#define NC 100000
#define NM 20000
typedef unsigned int u32; typedef unsigned long long u64;
typedef __nv_bfloat16 bf;

// ---------------- fp32 scratch ----------------
static constexpr size_t
 F_HC=0,                    F_HM=F_HC+(size_t)NC*128,
 F_SC=F_HM+(size_t)NM*128,  F_SM=F_SC+(size_t)NC*128,
 F_GC=F_SM+(size_t)NM*128,  F_GM=F_GC+(size_t)NC*64,
 F_Q2=F_GM+(size_t)NM*64,   F_RSC=F_Q2+(size_t)NT*64,
 F_RSM=F_RSC+NC, F_TOT=F_RSM+NM;
__device__ float g_f[F_TOT];

// ---------------- bf16 scratch ----------------
static constexpr size_t
 B_P1H=0,                     B_P1L=B_P1H+(size_t)NT*256,
 B_P2H=B_P1L+(size_t)NT*256,  B_P2L=B_P2H+(size_t)NT*256,
 B_ACH=B_P2L+(size_t)NT*256,  B_ACL=B_ACH+(size_t)NC*128,
 B_AMH=B_ACL+(size_t)NC*128,  B_AML=B_AMH+(size_t)NM*128,
 B_TH=B_AML+(size_t)NM*128,   B_TL=B_TH+(size_t)NT*64,
 B_Q1H=B_TL+(size_t)NT*64,    B_Q1L=B_Q1H+(size_t)NT*64,
 SZ_P1=(size_t)256*416, SZ_P2=65536, SZ_P3=32768, SZ_CV=16384, SZ_C3=8192, SZ_PO=4096,
 W_P1=B_Q1L+(size_t)NT*64,
 W_P2=W_P1+2*SZ_P1, W_P3=W_P2+2*SZ_P2,
 W_C1=W_P3+2*SZ_P3,
 W_C2=W_C1+8*SZ_CV, W_C3=W_C2+8*SZ_CV,
 W_PI=W_C3+4*SZ_C3, W_PH=W_PI+2*SZ_PO,
 B_TOT=W_PH+2*SZ_PO;
__device__ bf g_b[B_TOT];

// ---------------- PTX helpers ----------------
__device__ __forceinline__ u32 smem_u32(const void* p){
    u32 a; asm("{ .reg .u64 t; cvta.to.shared.u64 t, %1; cvt.u32.u64 %0, t; }":"=r"(a):"l"(p));
    return a;
}
__device__ __forceinline__ u32 packpair(float a, float b){ // low half=a, high=b
    u32 r; asm("cvt.rn.bf16x2.f32 %0, %1, %2;" : "=r"(r) : "f"(b), "f"(a)); return r;
}
__device__ __forceinline__ float bflo(u32 p){ return __uint_as_float(p<<16); }
__device__ __forceinline__ float bfhi(u32 p){ return __uint_as_float(p&0xFFFF0000u); }

__device__ __forceinline__ void cpa16(u32 dst, const void* src, int sz){
    asm volatile("cp.async.cg.shared.global [%0], [%1], 16, %2;"
                 :: "r"(dst), "l"(src), "r"(sz) : "memory");
}
#define CP_COMMIT() asm volatile("cp.async.commit_group;" ::: "memory")
#define CP_WAIT(n)  asm volatile("cp.async.wait_group %0;" :: "n"(n) : "memory")
#define STS128(a,x0,x1,x2,x3) asm volatile("st.shared.v4.b32 [%0], {%1,%2,%3,%4};" :: "r"(a), "r"(x0),"r"(x1),"r"(x2),"r"(x3))

__device__ __forceinline__ void ldm4(u32* d, u32 a){
    asm volatile("ldmatrix.sync.aligned.m8n8.x4.shared.b16 {%0,%1,%2,%3}, [%4];"
        : "=r"(d[0]),"=r"(d[1]),"=r"(d[2]),"=r"(d[3]) : "r"(a));
}
__device__ __forceinline__ void mma16816(float* c, const u32* a, const u32* b){
    asm volatile("mma.sync.aligned.m16n8k16.row.col.f32.bf16.bf16.f32 "
        "{%0,%1,%2,%3}, {%4,%5,%6,%7}, {%8,%9}, {%0,%1,%2,%3};"
        : "+f"(c[0]),"+f"(c[1]),"+f"(c[2]),"+f"(c[3])
        : "r"(a[0]),"r"(a[1]),"r"(a[2]),"r"(a[3]), "r"(b[0]),"r"(b[1]));
}
__device__ __forceinline__ void redadd2(float* p, float a, float b){
    asm volatile("red.relaxed.gpu.global.add.v2.f32 [%0], {%1,%2};"
                 :: "l"(p), "f"(a), "f"(b) : "memory");
}

// ---------------- small kernels ----------------
__global__ void zero_kernel(float* p, size_t n)
{
    size_t i = (size_t)blockIdx.x*blockDim.x + threadIdx.x;
    if (i < n) p[i] = 0.f;
}
__global__ void wsplit_kernel(const float* __restrict__ W0, int K, int N, int Kpad,
                              size_t wstride, size_t ostride,
                              bf* __restrict__ H0, bf* __restrict__ L0)
{
    int b = blockIdx.y;
    const float* W = W0 + (size_t)b*wstride;
    bf* H = H0 + (size_t)b*ostride;
    bf* L = L0 + (size_t)b*ostride;
    int i = blockIdx.x*blockDim.x + threadIdx.x;
    int hp = Kpad>>1;
    if (i >= N*hp) return;
    int n = i/hp, k = (i%hp)*2;
    float a0 = (k   < K) ? W[(size_t)k*N+n]     : 0.f;
    float a1 = (k+1 < K) ? W[(size_t)(k+1)*N+n] : 0.f;
    u32 h = packpair(a0,a1);
    u32 l = packpair(a0-bflo(h), a1-bfhi(h));
    *(u32*)(H + (size_t)n*Kpad + k) = h;
    *(u32*)(L + (size_t)n*Kpad + k) = l;
}

// ---------------- mma.sync GEMM (dual-problem capable) ----------------
// Problem 1 covers grid.y tiles [0, ty1); problem 2 (if M2>0) the rest.
template<int BNT, bool CVTA>
__global__ void __launch_bounds__(256, 2)
hgemm_kernel(const void* __restrict__ Aptr_, const bf* __restrict__ AL_,
             const bf* __restrict__ BH_, const bf* __restrict__ BL_,
             int M_, int Kpad, int Ald, int Kreal, int ldC,
             const float* __restrict__ preA_,
             const float* __restrict__ bias_, const float* __restrict__ sC_, int relu,
             float* __restrict__ outF_, bf* __restrict__ outH_, bf* __restrict__ outL_,
             const float* __restrict__ esc_,
             const int* __restrict__ scid, const int* __restrict__ smid,
             float* __restrict__ scC, float* __restrict__ scM,
             int ty1, int M2,
             const void* __restrict__ A2, const bf* __restrict__ AL2,
             const bf* __restrict__ BH2, const bf* __restrict__ BL2,
             const float* __restrict__ preA2, const float* __restrict__ bias2,
             const float* __restrict__ sC2,
             float* __restrict__ outF2, bf* __restrict__ outH2, bf* __restrict__ outL2,
             const float* __restrict__ esc2)
{
    extern __shared__ char smem[];
    constexpr int STG = 16384 + BNT*128;     // A(hi+lo) 16KB + B(hi+lo)
    constexpr int WN  = BNT/2;
    constexpr int NTI = WN/8;
    const u32 smb = smem_u32(smem);
    const int tid = threadIdx.x, w = tid>>5, l = tid&31;
    const int wm = w>>1, wn = w&1;

    // problem select
    const void* Aptr = Aptr_; const bf* AL = AL_;
    const bf* BHp = BH_; const bf* BLp = BL_;
    int M = M_;
    const float* preA = preA_; const float* bias = bias_; const float* sC = sC_;
    float* outF = outF_; bf* outH = outH_; bf* outL = outL_; const float* esc = esc_;
    int by = blockIdx.y;
    if (M2 > 0 && by >= ty1) {
        by -= ty1; M = M2; Aptr = A2; AL = AL2; BHp = BH2; BLp = BL2;
        preA = preA2; bias = bias2; sC = sC2;
        outF = outF2; outH = outH2; outL = outL2; esc = esc2;
    }
    const int row0 = by*128;
    const int col0 = blockIdx.x*BNT;

    const bf* AHb = (const bf*)Aptr;
    const float* Af = (const float*)Aptr;
    const bf* Bh = BHp + (size_t)col0*Kpad;
    const bf* Bl = BLp + (size_t)col0*Kpad;

    const int nst = Kpad >> 5;
    float aReg[16];

    auto ldgA = [&](int st){
        if (!CVTA) return;
        const int k0 = st<<5;
#pragma unroll
        for (int j = 0; j < 2; j++) {
            int i = tid*2 + j;
            int r = i>>2, cch = i&3;
            int gr = row0 + r;
            float* v = aReg + j*8;
            if (gr < M) {
                const float* p = Af + (size_t)gr*Ald + k0 + cch*8;
                int kb = k0 + cch*8;
                if ((Ald&3)==0 && kb + 8 <= Kreal) {
                    float4 q0 = *(const float4*)p, q1 = *(const float4*)(p+4);
                    v[0]=q0.x; v[1]=q0.y; v[2]=q0.z; v[3]=q0.w;
                    v[4]=q1.x; v[5]=q1.y; v[6]=q1.z; v[7]=q1.w;
                } else {
#pragma unroll
                    for (int e = 0; e < 4; e++) {
                        int k = kb + 2*e;
                        if (k + 2 <= Kreal) {
                            float2 q = *(const float2*)(p + 2*e);
                            v[2*e] = q.x; v[2*e+1] = q.y;
                        } else if (k < Kreal) {
                            v[2*e] = p[2*e]; v[2*e+1] = 0.f;
                        } else { v[2*e] = 0.f; v[2*e+1] = 0.f; }
                    }
                }
                if (preA) {
                    float s = preA[gr];
#pragma unroll
                    for (int e = 0; e < 8; e++) v[e] *= s;
                }
            } else {
#pragma unroll
                for (int e = 0; e < 8; e++) v[e] = 0.f;
            }
        }
    };
    auto stsA = [&](int buf){
        if (!CVTA) return;
        const u32 sb = smb + buf*STG;
#pragma unroll
        for (int j = 0; j < 2; j++) {
            int i = tid*2 + j;
            int r = i>>2, cch = i&3;
            float* v = aReg + j*8;
            u32 h[4], lo[4];
#pragma unroll
            for (int e = 0; e < 4; e++) {
                h[e]  = packpair(v[2*e], v[2*e+1]);
                lo[e] = packpair(v[2*e]-bflo(h[e]), v[2*e+1]-bfhi(h[e]));
            }
            u32 d = sb + r*64 + ((u32)(cch ^ ((r>>1)&3))<<4);
            STS128(d,        h[0],h[1],h[2],h[3]);
            STS128(d + 8192, lo[0],lo[1],lo[2],lo[3]);
        }
    };
    auto issue = [&](int st, int buf){
        const u32 sb = smb + buf*STG;
        const int k0 = st<<5;
        if (!CVTA) {
            for (int i = tid; i < 512; i += 256) {        // A: 128 rows x 4 chunks
                int r = i>>2, cch = i&3;
                int gr = row0 + r;
                int grc = gr < M ? gr : 0;
                int sz  = gr < M ? 16 : 0;
                u32 d = sb + r*64 + ((u32)(cch ^ ((r>>1)&3))<<4);
                cpa16(d,        AHb + (size_t)grc*Ald + k0 + cch*8, sz);
                cpa16(d + 8192, AL  + (size_t)grc*Ald + k0 + cch*8, sz);
            }
        }
        for (int i = tid; i < BNT*4; i += 256) {          // B: BNT rows x 4 chunks
            int r = i>>2, cch = i&3;
            u32 d = sb + 16384 + r*64 + ((u32)(cch ^ ((r>>1)&3))<<4);
            cpa16(d,          Bh + (size_t)r*Kpad + k0 + cch*8, 16);
            cpa16(d + BNT*64, Bl + (size_t)r*Kpad + k0 + cch*8, 16);
        }
        CP_COMMIT();
    };

    float acc[2][NTI][4];
#pragma unroll
    for (int mt = 0; mt < 2; mt++)
#pragma unroll
        for (int nt = 0; nt < NTI; nt++)
#pragma unroll
            for (int q = 0; q < 4; q++) acc[mt][nt][q] = 0.f;

    ldgA(0);
    issue(0, 0);
    if (nst > 1) issue(1, 1);

    int bufc = 0;
    for (int c = 0; c < nst; c++) {
        if (c + 1 < nst) CP_WAIT(1); else CP_WAIT(0);
        if (CVTA) {
            stsA(bufc);
            if (c + 1 < nst) ldgA(c + 1);
        }
        __syncthreads();                     // the ONLY barrier per stage
        if (c + 2 < nst) {
            int nb = bufc + 2; if (nb >= 3) nb -= 3;
            issue(c + 2, nb);
        }
        const u32 sa  = smb + bufc*STG;
        const u32 sbB = sa + 16384;
#pragma unroll
        for (int ks = 0; ks < 2; ks++) {
            u32 ah[2][4], al2[2][4];
#pragma unroll
            for (int mt = 0; mt < 2; mt++) {
                int r  = wm*32 + mt*16 + (l&15);
                int ch = (ks*2 + (l>>4)) ^ ((r>>1)&3);
                u32 ad = sa + r*64 + ch*16;
                ldm4(ah[mt],  ad);
                ldm4(al2[mt], ad + 8192);
            }
            u32 bh2[NTI][2], bl2[NTI][2];
#pragma unroll
            for (int tp = 0; tp < NTI; tp += 2) {
                int r  = wn*WN + (tp + (l>>4))*8 + (l&7);
                int ch = (ks*2 + ((l>>3)&1)) ^ ((r>>1)&3);
                u32 ad = sbB + r*64 + ch*16;
                u32 t4[4]; ldm4(t4, ad);
                bh2[tp][0]=t4[0]; bh2[tp][1]=t4[1]; bh2[tp+1][0]=t4[2]; bh2[tp+1][1]=t4[3];
                u32 t5[4]; ldm4(t5, ad + BNT*64);
                bl2[tp][0]=t5[0]; bl2[tp][1]=t5[1]; bl2[tp+1][0]=t5[2]; bl2[tp+1][1]=t5[3];
            }
#pragma unroll
            for (int mt = 0; mt < 2; mt++)
#pragma unroll
                for (int nt = 0; nt < NTI; nt++)
                    mma16816(acc[mt][nt], ah[mt], bh2[nt]);
#pragma unroll
            for (int mt = 0; mt < 2; mt++)
#pragma unroll
                for (int nt = 0; nt < NTI; nt++)
                    mma16816(acc[mt][nt], ah[mt], bl2[nt]);
#pragma unroll
            for (int mt = 0; mt < 2; mt++)
#pragma unroll
                for (int nt = 0; nt < NTI; nt++)
                    mma16816(acc[mt][nt], al2[mt], bh2[nt]);
        }
        bufc = (bufc == 2) ? 0 : bufc + 1;
    }

    // epilogue
#pragma unroll
    for (int mt = 0; mt < 2; mt++)
#pragma unroll
        for (int hf = 0; hf < 2; hf++) {
            int r = row0 + wm*32 + mt*16 + (l>>2) + hf*8;
            if (r >= M) continue;
            float scv = sC  ? sC[r]  : 1.f;
            float e   = esc ? esc[r] : 1.f;
            int ci = 0, mi = 0;
            if (scC) { ci = scid[r]; mi = smid[r]; }
#pragma unroll
            for (int nt = 0; nt < NTI; nt++) {
                int col = col0 + wn*WN + nt*8 + (l&3)*2;
                float v0 = acc[mt][nt][hf*2], v1 = acc[mt][nt][hf*2+1];
                if (sC)   { v0 *= scv; v1 *= scv; }
                if (bias) { v0 += bias[col]; v1 += bias[col+1]; }
                if (relu) { v0 = fmaxf(v0,0.f); v1 = fmaxf(v1,0.f); }
                if (scC) {
                    redadd2(scC + (size_t)ci*128 + col, v0, v1);
                    redadd2(scM + (size_t)mi*128 + col, v0, v1);
                }
                if (outF) *(float2*)(outF + (size_t)r*ldC + col) = make_float2(v0,v1);
                if (outH) {
                    float a0 = v0*e, a1 = v1*e;
                    u32 h = packpair(a0,a1);
                    u32 lo = packpair(a0-bflo(h), a1-bfhi(h));
                    *(u32*)(outH + (size_t)r*ldC + col) = h;
                    *(u32*)(outL + (size_t)r*ldC + col) = lo;
                }
            }
        }
}

// ---------------- graph-side kernels ----------------
__global__ void deg_count_kernel(const int* __restrict__ cid, const int* __restrict__ mid,
                                 float* degC, float* degM, int n)
{
    int i = blockIdx.x*blockDim.x + threadIdx.x;
    if (i < n) { atomicAdd(&degC[cid[i]], 1.f); atomicAdd(&degM[mid[i]], 1.f); }
}
__global__ void rsqrt_kernel(float* d, int n)
{
    int i = blockIdx.x*blockDim.x + threadIdx.x;
    if (i < n) d[i] = rsqrtf(fmaxf(d[i], 1.f));
}
__global__ void gather_segsum_kernel(const float* __restrict__ hc, const float* __restrict__ hm,
                                     const int* __restrict__ cid, const int* __restrict__ mid,
                                     const float* __restrict__ ba, const float* __restrict__ bb,
                                     float* outC, float* outM, int n)
{
    int w = (blockIdx.x*blockDim.x + threadIdx.x)>>5, lane = threadIdx.x&31;
    if (w >= n) return;
    int c = cid[w], m = mid[w];
    int col = lane*4;
    float4 x = *(const float4*)(hc + (size_t)c*128 + col);
    float4 y = *(const float4*)(hm + (size_t)m*128 + col);
    float4 u = *(const float4*)(ba + col);
    float4 v = *(const float4*)(bb + col);
    float z0 = fmaxf(x.x+y.x+u.x+v.x, 0.f), z1 = fmaxf(x.y+y.y+u.y+v.y, 0.f);
    float z2 = fmaxf(x.z+y.z+u.z+v.z, 0.f), z3 = fmaxf(x.w+y.w+u.w+v.w, 0.f);
    float* pc = outC + (size_t)c*128 + col;
    float* pm = outM + (size_t)m*128 + col;
    asm volatile("red.relaxed.gpu.global.add.v4.f32 [%0], {%1,%2,%3,%4};" :: "l"(pc),"f"(z0),"f"(z1),"f"(z2),"f"(z3) : "memory");
    asm volatile("red.relaxed.gpu.global.add.v4.f32 [%0], {%1,%2,%3,%4};" :: "l"(pm),"f"(z0),"f"(z1),"f"(z2),"f"(z3) : "memory");
}
__global__ void gather_dot_kernel(const float* __restrict__ hc, const float* __restrict__ hm,
                                  const int* __restrict__ cid, const int* __restrict__ mid,
                                  const float* __restrict__ ba, const float* __restrict__ bb,
                                  const float* __restrict__ w3,
                                  float* outC, float* outM, int n)
{
    int w = (blockIdx.x*blockDim.x + threadIdx.x)>>5, lane = threadIdx.x&31;
    if (w >= n) return;
    int c = cid[w], m = mid[w];
    int col = lane*4;
    float4 x = *(const float4*)(hc + (size_t)c*128 + col);
    float4 y = *(const float4*)(hm + (size_t)m*128 + col);
    float4 u = *(const float4*)(ba + col);
    float4 v = *(const float4*)(bb + col);
    float z0 = fmaxf(x.x+y.x+u.x+v.x, 0.f), z1 = fmaxf(x.y+y.y+u.y+v.y, 0.f);
    float z2 = fmaxf(x.z+y.z+u.z+v.z, 0.f), z3 = fmaxf(x.w+y.w+u.w+v.w, 0.f);
    float4 w0 = *(const float4*)(w3 + col);
    float4 w1 = *(const float4*)(w3 + 128 + col);
    float s0 = z0*w0.x + z1*w0.y + z2*w0.z + z3*w0.w;
    float s1 = z0*w1.x + z1*w1.y + z2*w1.z + z3*w1.w;
#pragma unroll
    for (int o = 16; o; o >>= 1) {
        s0 += __shfl_xor_sync(0xffffffffu, s0, o);
        s1 += __shfl_xor_sync(0xffffffffu, s1, o);
    }
    if (lane == 0) { atomicAdd(&outC[c], s0); atomicAdd(&outM[m], s1); }
}
__global__ void gather_hl_kernel(const float* __restrict__ gc, const float* __restrict__ gm,
                                 const int* __restrict__ cid, const int* __restrict__ mid,
                                 const float* __restrict__ ba, const float* __restrict__ bb,
                                 bf* __restrict__ oh, bf* __restrict__ ol, int n)
{
    int w = (blockIdx.x*blockDim.x + threadIdx.x)>>5, lane = threadIdx.x&31;
    if (w >= n) return;
    int c = cid[w], m = mid[w];
    float2 x = *(const float2*)(gc + (size_t)c*64 + lane*2);
    float2 y = *(const float2*)(gm + (size_t)m*64 + lane*2);
    float2 u = *(const float2*)(ba + lane*2);
    float2 v = *(const float2*)(bb + lane*2);
    float a0 = x.x+y.x+u.x+v.x, a1 = x.y+y.y+u.y+v.y;
    u32 h = packpair(a0,a1);
    u32 l = packpair(a0-bflo(h), a1-bfhi(h));
    *(u32*)(oh + (size_t)w*64 + lane*2) = h;
    *(u32*)(ol + (size_t)w*64 + lane*2) = l;
}
__global__ void finalize_cm_kernel(float* outC, float* outM,
                                   const float* __restrict__ rsC, const float* __restrict__ rsM,
                                   const float* __restrict__ bo, int nc, int nm)
{
    int i = blockIdx.x*blockDim.x + threadIdx.x;
    if (i < nc)              outC[i]    = outC[i]*rsC[i] + bo[0];
    else if (i < nc + nm)    outM[i-nc] = outM[i-nc]*rsM[i-nc] + bo[1];
}
__global__ void gemv64_kernel(const float* __restrict__ A, const float* __restrict__ w,
                              const float* __restrict__ b, float* __restrict__ out, int n)
{
    int r = (blockIdx.x*blockDim.x + threadIdx.x)>>5, lane = threadIdx.x&31;
    if (r >= n) return;
    float2 x  = *(const float2*)(A + (size_t)r*64 + lane*2);
    float2 ww = *(const float2*)(w + lane*2);
    float s = x.x*ww.x + x.y*ww.y;
#pragma unroll
    for (int o = 16; o; o >>= 1) s += __shfl_xor_sync(0xffffffffu, s, o);
    if (lane == 0) out[r] = s + b[0];
}

// ---------------- host ----------------
struct Prob {
    const void* A; const bf* AL; const bf* BH; const bf* BL;
    int M; const float* preA; const float* bias; const float* sC;
    float* outF; bf* outH; bf* outL; const float* esc;
};
static void launch_g(int BN, bool cvta, const Prob& p1, const Prob* p2,
                     int Kpad, int Ald, int Kreal, int relu, int ldC,
                     const int* scid = nullptr, const int* smid = nullptr,
                     float* scC = nullptr, float* scM = nullptr)
{
    int ty1 = (p1.M + 127)/128;
    int ty  = ty1 + (p2 ? (p2->M + 127)/128 : 0);
    Prob z = {};
    const Prob& q = p2 ? *p2 : z;
    if (BN >= 128) {
        dim3 g(BN/128, ty);
        size_t sm = 3*(16384 + 128*128);
        if (cvta) {
            cudaFuncSetAttribute(hgemm_kernel<128,true>, cudaFuncAttributeMaxDynamicSharedMemorySize, (int)sm);
            hgemm_kernel<128,true><<<g, 256, sm>>>(p1.A,p1.AL,p1.BH,p1.BL,p1.M,Kpad,Ald,Kreal,ldC,
                p1.preA,p1.bias,p1.sC,relu,p1.outF,p1.outH,p1.outL,p1.esc,scid,smid,scC,scM,
                ty1, p2?q.M:0, q.A,q.AL,q.BH,q.BL,q.preA,q.bias,q.sC,q.outF,q.outH,q.outL,q.esc);
        } else {
            cudaFuncSetAttribute(hgemm_kernel<128,false>, cudaFuncAttributeMaxDynamicSharedMemorySize, (int)sm);
            hgemm_kernel<128,false><<<g, 256, sm>>>(p1.A,p1.AL,p1.BH,p1.BL,p1.M,Kpad,Ald,Kreal,ldC,
                p1.preA,p1.bias,p1.sC,relu,p1.outF,p1.outH,p1.outL,p1.esc,scid,smid,scC,scM,
                ty1, p2?q.M:0, q.A,q.AL,q.BH,q.BL,q.preA,q.bias,q.sC,q.outF,q.outH,q.outL,q.esc);
        }
    } else {
        dim3 g(1, ty);
        size_t sm = 3*(16384 + 64*128);
        if (cvta) {
            cudaFuncSetAttribute(hgemm_kernel<64,true>, cudaFuncAttributeMaxDynamicSharedMemorySize, (int)sm);
            hgemm_kernel<64,true><<<g, 256, sm>>>(p1.A,p1.AL,p1.BH,p1.BL,p1.M,Kpad,Ald,Kreal,ldC,
                p1.preA,p1.bias,p1.sC,relu,p1.outF,p1.outH,p1.outL,p1.esc,scid,smid,scC,scM,
                ty1, p2?q.M:0, q.A,q.AL,q.BH,q.BL,q.preA,q.bias,q.sC,q.outF,q.outH,q.outL,q.esc);
        } else {
            cudaFuncSetAttribute(hgemm_kernel<64,false>, cudaFuncAttributeMaxDynamicSharedMemorySize, (int)sm);
            hgemm_kernel<64,false><<<g, 256, sm>>>(p1.A,p1.AL,p1.BH,p1.BL,p1.M,Kpad,Ald,Kreal,ldC,
                p1.preA,p1.bias,p1.sC,relu,p1.outF,p1.outH,p1.outL,p1.esc,scid,smid,scC,scM,
                ty1, p2?q.M:0, q.A,q.AL,q.BH,q.BL,q.preA,q.bias,q.sC,q.outF,q.outH,q.outL,q.esc);
        }
    }
}
static void wsp(const float* W, int K, int N, int Kpad, bf* H, bf* L,
                int count = 1, size_t wstride = 0, size_t ostride = 0)
{
    int n = N*(Kpad/2);
    dim3 g((n + 255)/256, count);
    wsplit_kernel<<<g, 256>>>(W, K, N, Kpad, wstride, ostride, H, L);
}

extern "C" void kernel_launch(void* const* d_in, const int* in_sizes, int n_in,
                              void* d_out, int out_size)
{
    const float* X      = (const float*)d_in[0];
    const int*   cid    = (const int*)  d_in[1];
    const int*   mid    = (const int*)  d_in[2];
    const float* cardE  = (const float*)d_in[3];
    const float* merchE = (const float*)d_in[4];
    const float* preWi  = (const float*)d_in[5];
    const float* preBi  = (const float*)d_in[6];
    const float* preWh  = (const float*)d_in[7];
    const float* preBh  = (const float*)d_in[8];
    const float* preWo  = (const float*)d_in[9];
    const float* preBo  = (const float*)d_in[10];
    const float* c1W    = (const float*)d_in[11];
    const float* c1b    = (const float*)d_in[12];
    const float* c2W    = (const float*)d_in[13];
    const float* c2b    = (const float*)d_in[14];
    const float* c3Wt   = (const float*)d_in[15];
    const float* c3bt   = (const float*)d_in[16];
    const float* c3Wo   = (const float*)d_in[17];
    const float* c3bo   = (const float*)d_in[18];
    const float* poWi   = (const float*)d_in[19];
    const float* poBi   = (const float*)d_in[20];
    const float* poWh   = (const float*)d_in[21];
    const float* poBh   = (const float*)d_in[22];
    const float* poWo   = (const float*)d_in[23];
    const float* poBo   = (const float*)d_in[24];
    float* out = (float*)d_out;

    float* F = nullptr; bf* B = nullptr;
    cudaGetSymbolAddress((void**)&F, g_f);
    cudaGetSymbolAddress((void**)&B, g_b);

    float *HC=F+F_HC, *HM=F+F_HM, *SC=F+F_SC, *SM=F+F_SM,
          *GC=F+F_GC, *GM=F+F_GM, *Q2=F+F_Q2, *rsC=F+F_RSC, *rsM=F+F_RSM;

    const int wpr = (NT*32 + 255)/256;

    // launches 1-3
    wsp(preWi, 390, 256, 416, B+W_P1, B+W_P1+SZ_P1);                 // 1
    zero_kernel<<<(NC+NM+255)/256, 256>>>(rsC, NC+NM);               // 2
    deg_count_kernel<<<(NT+255)/256, 256>>>(cid, mid, rsC, rsM, NT); // 3
    // launch 4 (ncu capture slot): dominant pre-FF GEMM, fused X split
    {
        Prob p1 = {X, nullptr, B+W_P1, B+W_P1+SZ_P1, NT, nullptr, preBi, nullptr,
                   nullptr, B+B_P1H, B+B_P1L, nullptr};
        launch_g(256, true, p1, nullptr, 416, 390, 390, 1, 256);
    }
    rsqrt_kernel<<<(NC+NM+255)/256, 256>>>(rsC, NC+NM);              // 5

    // remaining weight splits (batched)
    wsp(preWh, 256, 256, 256, B+W_P2, B+W_P2+SZ_P2);
    wsp(preWo, 256, 128, 256, B+W_P3, B+W_P3+SZ_P3);
    wsp(c1W, 128, 128, 128, B+W_C1, B+W_C1+SZ_CV, 4, 16384, 2*SZ_CV);
    wsp(c2W, 128, 128, 128, B+W_C2, B+W_C2+SZ_CV, 4, 16384, 2*SZ_CV);
    wsp(c3Wt, 128, 64, 128, B+W_C3, B+W_C3+SZ_C3, 2, 8192, 2*SZ_C3);
    wsp(poWi, 64, 64, 64, B+W_PI, B+W_PI+SZ_PO);
    wsp(poWh, 64, 64, 64, B+W_PH, B+W_PH+SZ_PO);

    // zero SC/SM ahead of the scatter-epilogue GEMM3
    zero_kernel<<<(unsigned)(((size_t)(NC+NM)*128 + 255)/256), 256>>>(SC, (size_t)(NC+NM)*128);

    // pre-FF rest
    {
        Prob p1 = {B+B_P1H, B+B_P1L, B+W_P2, B+W_P2+SZ_P2, NT, nullptr, preBh, nullptr,
                   nullptr, B+B_P2H, B+B_P2L, nullptr};
        launch_g(256, false, p1, nullptr, 256, 256, 256, 1, 256);
    }
    {   // 256->128 with fused segsum#1 scatter (TF eliminated)
        Prob p1 = {B+B_P2H, B+B_P2L, B+W_P3, B+W_P3+SZ_P3, NT, nullptr, preBo, nullptr,
                   nullptr, nullptr, nullptr, nullptr};
        launch_g(128, false, p1, nullptr, 256, 256, 256, 0, 128, cid, mid, SC, SM);
    }

    // conv1 fwd (dual: card + merch, fp32 embeddings + deg prescale)
    {
        Prob p1 = {cardE,  nullptr, B+W_C1+0*2*SZ_CV, B+W_C1+0*2*SZ_CV+SZ_CV, NC, rsC, nullptr, nullptr, HC, nullptr, nullptr, nullptr};
        Prob p2 = {merchE, nullptr, B+W_C1+1*2*SZ_CV, B+W_C1+1*2*SZ_CV+SZ_CV, NM, rsM, nullptr, nullptr, HM, nullptr, nullptr, nullptr};
        launch_g(128, true, p1, &p2, 128, 128, 128, 0, 128);
    }
    // conv1 rev (dual)
    {
        Prob p1 = {SC, nullptr, B+W_C1+2*2*SZ_CV, B+W_C1+2*2*SZ_CV+SZ_CV, NC, nullptr, c1b+256, rsC, nullptr, B+B_ACH, B+B_ACL, rsC};
        Prob p2 = {SM, nullptr, B+W_C1+3*2*SZ_CV, B+W_C1+3*2*SZ_CV+SZ_CV, NM, nullptr, c1b+384, rsM, nullptr, B+B_AMH, B+B_AML, rsM};
        launch_g(128, true, p1, &p2, 128, 128, 128, 1, 128);
    }

    // segsum#2 fused with gather1 (HT1 eliminated)
    zero_kernel<<<(unsigned)(((size_t)(NC+NM)*128 + 255)/256), 256>>>(SC, (size_t)(NC+NM)*128);
    gather_segsum_kernel<<<wpr, 256>>>(HC, HM, cid, mid, c1b, c1b+128, SC, SM, NT);

    // conv2 fwd (dual; overwrites HC/HM — safe now)
    {
        Prob p1 = {B+B_ACH, B+B_ACL, B+W_C2+0*2*SZ_CV, B+W_C2+0*2*SZ_CV+SZ_CV, NC, nullptr, nullptr, nullptr, HC, nullptr, nullptr, nullptr};
        Prob p2 = {B+B_AMH, B+B_AML, B+W_C2+1*2*SZ_CV, B+W_C2+1*2*SZ_CV+SZ_CV, NM, nullptr, nullptr, nullptr, HM, nullptr, nullptr, nullptr};
        launch_g(128, false, p1, &p2, 128, 128, 128, 0, 128);
    }

    // conv3 non-target heads fused with gather2 (HT2 eliminated)
    cudaMemsetAsync(out + NT, 0, (size_t)(NC+NM)*4, 0);
    gather_dot_kernel<<<wpr, 256>>>(HC, HM, cid, mid, c2b, c2b+128, c3Wo, out+NT, out+NT+NC, NT);

    // conv2 rev (dual)
    {
        Prob p1 = {SC, nullptr, B+W_C2+2*2*SZ_CV, B+W_C2+2*2*SZ_CV+SZ_CV, NC, nullptr, c2b+256, rsC, nullptr, B+B_ACH, B+B_ACL, rsC};
        Prob p2 = {SM, nullptr, B+W_C2+3*2*SZ_CV, B+W_C2+3*2*SZ_CV+SZ_CV, NM, nullptr, c2b+384, rsM, nullptr, B+B_AMH, B+B_AML, rsM};
        launch_g(128, true, p1, &p2, 128, 128, 128, 1, 128);
    }

    // conv3 target-side D_OUT=64 (dual)
    {
        Prob p1 = {B+B_ACH, B+B_ACL, B+W_C3+0*2*SZ_C3, B+W_C3+0*2*SZ_C3+SZ_C3, NC, nullptr, nullptr, nullptr, GC, nullptr, nullptr, nullptr};
        Prob p2 = {B+B_AMH, B+B_AML, B+W_C3+1*2*SZ_C3, B+W_C3+1*2*SZ_C3+SZ_C3, NM, nullptr, nullptr, nullptr, GM, nullptr, nullptr, nullptr};
        launch_g(64, false, p1, &p2, 128, 128, 128, 0, 64);
    }
    gather_hl_kernel<<<wpr, 256>>>(GC, GM, cid, mid, c3bt, c3bt+64, B+B_TH, B+B_TL, NT);

    finalize_cm_kernel<<<(NC+NM+255)/256, 256>>>(out+NT, out+NT+NC, rsC, rsM, c3bo, NC, NM);

    // post-FF: 64->64->64->1
    {
        Prob p1 = {B+B_TH, B+B_TL, B+W_PI, B+W_PI+SZ_PO, NT, nullptr, poBi, nullptr,
                   nullptr, B+B_Q1H, B+B_Q1L, nullptr};
        launch_g(64, false, p1, nullptr, 64, 64, 64, 1, 64);
    }
    {
        Prob p1 = {B+B_Q1H, B+B_Q1L, B+W_PH, B+W_PH+SZ_PO, NT, nullptr, poBh, nullptr,
                   Q2, nullptr, nullptr, nullptr};
        launch_g(64, false, p1, nullptr, 64, 64, 64, 1, 64);
    }
    gemv64_kernel<<<wpr, 256>>>(Q2, poWo, poBo, out, NT);
}